// round 1
// baseline (speedup 1.0000x reference)
#include <cuda_runtime.h>
#include <math.h>

// Problem constants
#define B 8
#define NTOK 1024
#define E 768
#define H 8
#define D 96
#define BHM (B * H)                 // 64 batch-heads
#define MROWS (B * NTOK)            // 8192

// ---------------- device scratch (no allocations allowed) ----------------
__device__ float g_Q[B * H * NTOK * D];     // [b,h,m,d]  25.2 MB
__device__ float g_K[B * H * NTOK * D];     // [b,h,p,d]
__device__ float g_V[B * H * NTOK * D];     // [b,h,p,d]
__device__ float g_S[(size_t)BHM * NTOK * NTOK];  // [b,h,m,p] scores->probs, 256 MB
__device__ float g_A[B * NTOK * E];         // attended pre-O, [b,m,h*D+d]

// ---------------------------------------------------------------------------
// Linear: C[M,768] = X[M,768] @ W[768,768]^T + bias
// QKV=1: scatter output to [b,h,m,d] layout; QKV=0: plain row-major [M,768]
// Tiles: BM=BN=64, BK=16, 256 threads, 4x4 per thread.
// ---------------------------------------------------------------------------
template <int QKV>
__global__ void linear_kernel(const float* __restrict__ X,
                              const float* __restrict__ W,
                              const float* __restrict__ bias,
                              float* __restrict__ out) {
    __shared__ float As[16][65];
    __shared__ float Bs[16][65];

    const int tid = threadIdx.x;
    const int tx = tid & 15;
    const int ty = tid >> 4;
    const int row0 = blockIdx.y * 64;
    const int col0 = blockIdx.x * 64;

    float acc[4][4];
#pragma unroll
    for (int i = 0; i < 4; i++)
#pragma unroll
        for (int j = 0; j < 4; j++) acc[i][j] = 0.f;

    const int kk = tid & 15;   // k within tile
    const int mm = tid >> 4;   // row group base (0..15)

    for (int k0 = 0; k0 < E; k0 += 16) {
#pragma unroll
        for (int s = 0; s < 4; s++) {
            As[kk][mm + s * 16] = X[(size_t)(row0 + mm + s * 16) * E + k0 + kk];
            Bs[kk][mm + s * 16] = W[(size_t)(col0 + mm + s * 16) * E + k0 + kk];
        }
        __syncthreads();
#pragma unroll
        for (int k = 0; k < 16; k++) {
            float a[4], b[4];
#pragma unroll
            for (int i = 0; i < 4; i++) a[i] = As[k][ty + i * 16];
#pragma unroll
            for (int j = 0; j < 4; j++) b[j] = Bs[k][tx + j * 16];
#pragma unroll
            for (int i = 0; i < 4; i++)
#pragma unroll
                for (int j = 0; j < 4; j++) acc[i][j] += a[i] * b[j];
        }
        __syncthreads();
    }

#pragma unroll
    for (int i = 0; i < 4; i++) {
#pragma unroll
        for (int j = 0; j < 4; j++) {
            const int r = row0 + ty + i * 16;
            const int c = col0 + tx + j * 16;
            const float v = acc[i][j] + bias[c];
            if (QKV) {
                const int b = r >> 10;        // r / 1024
                const int m = r & 1023;
                const int h = c / D;
                const int d = c - h * D;
                out[((size_t)(b * H + h) * NTOK + m) * D + d] = v;
            } else {
                out[(size_t)r * E + c] = v;
            }
        }
    }
}

// ---------------------------------------------------------------------------
// Scores: per z=(b*H+h): S[m,p] = scale * dot(Q[z][m,:], K[z][p,:])
// Q,K are [1024,96] K-contiguous ("NT" gemm). BM=BN=64, BK=16.
// ---------------------------------------------------------------------------
__global__ void scores_kernel(const float* __restrict__ Q,
                              const float* __restrict__ K,
                              float* __restrict__ S, float scale) {
    __shared__ float As[16][65];
    __shared__ float Bs[16][65];

    const int z = blockIdx.z;
    const float* Qz = Q + (size_t)z * NTOK * D;
    const float* Kz = K + (size_t)z * NTOK * D;
    float* Sz = S + (size_t)z * NTOK * NTOK;

    const int tid = threadIdx.x;
    const int tx = tid & 15;
    const int ty = tid >> 4;
    const int row0 = blockIdx.y * 64;  // m
    const int col0 = blockIdx.x * 64;  // p

    float acc[4][4];
#pragma unroll
    for (int i = 0; i < 4; i++)
#pragma unroll
        for (int j = 0; j < 4; j++) acc[i][j] = 0.f;

    const int kk = tid & 15;
    const int mm = tid >> 4;

    for (int k0 = 0; k0 < D; k0 += 16) {
#pragma unroll
        for (int s = 0; s < 4; s++) {
            As[kk][mm + s * 16] = Qz[(size_t)(row0 + mm + s * 16) * D + k0 + kk];
            Bs[kk][mm + s * 16] = Kz[(size_t)(col0 + mm + s * 16) * D + k0 + kk];
        }
        __syncthreads();
#pragma unroll
        for (int k = 0; k < 16; k++) {
            float a[4], b[4];
#pragma unroll
            for (int i = 0; i < 4; i++) a[i] = As[k][ty + i * 16];
#pragma unroll
            for (int j = 0; j < 4; j++) b[j] = Bs[k][tx + j * 16];
#pragma unroll
            for (int i = 0; i < 4; i++)
#pragma unroll
                for (int j = 0; j < 4; j++) acc[i][j] += a[i] * b[j];
        }
        __syncthreads();
    }

#pragma unroll
    for (int i = 0; i < 4; i++)
#pragma unroll
        for (int j = 0; j < 4; j++)
            Sz[(size_t)(row0 + ty + i * 16) * NTOK + (col0 + tx + j * 16)] =
                acc[i][j] * scale;
}

// ---------------------------------------------------------------------------
// Row softmax in place. One block (256 threads) per row of 1024.
// ---------------------------------------------------------------------------
__global__ void softmax_kernel(float* __restrict__ S) {
    float* p = S + (size_t)blockIdx.x * NTOK;
    const int t = threadIdx.x;
    __shared__ float red[256];

    float x[4];
    float mx = -INFINITY;
#pragma unroll
    for (int s = 0; s < 4; s++) {
        x[s] = p[t + s * 256];
        mx = fmaxf(mx, x[s]);
    }
    red[t] = mx;
    __syncthreads();
    for (int o = 128; o > 0; o >>= 1) {
        if (t < o) red[t] = fmaxf(red[t], red[t + o]);
        __syncthreads();
    }
    mx = red[0];
    __syncthreads();

    float sum = 0.f;
#pragma unroll
    for (int s = 0; s < 4; s++) {
        x[s] = __expf(x[s] - mx);
        sum += x[s];
    }
    red[t] = sum;
    __syncthreads();
    for (int o = 128; o > 0; o >>= 1) {
        if (t < o) red[t] += red[t + o];
        __syncthreads();
    }
    const float inv = 1.f / red[0];
#pragma unroll
    for (int s = 0; s < 4; s++) p[t + s * 256] = x[s] * inv;
}

// ---------------------------------------------------------------------------
// attn_avg[b,m,p] = mean over h of P[b,h,m,p]. One block per (b,m).
// ---------------------------------------------------------------------------
__global__ void avg_kernel(const float* __restrict__ S, float* __restrict__ out) {
    const int bm = blockIdx.x;          // b*1024 + m
    const int b = bm >> 10;
    const int m = bm & 1023;
    const size_t base = ((size_t)b * H) * NTOK * NTOK + (size_t)m * NTOK;
#pragma unroll
    for (int s = 0; s < 4; s++) {
        const int p = threadIdx.x + s * 256;
        float acc = 0.f;
#pragma unroll
        for (int h = 0; h < H; h++)
            acc += S[base + (size_t)h * NTOK * NTOK + p];
        out[(size_t)bm * NTOK + p] = acc * (1.0f / H);
    }
}

// ---------------------------------------------------------------------------
// PV: per z=(b,h): C[1024,96] = P[1024,1024] @ V[1024,96]   (NN gemm)
// BM=64, BN=96 (full), BK=16, 256 threads, 4x6 per thread.
// Output written to g_A[(b*1024+m)*768 + h*96 + d].
// ---------------------------------------------------------------------------
__global__ void pv_kernel(const float* __restrict__ S,
                          const float* __restrict__ V,
                          float* __restrict__ A) {
    __shared__ float As[16][65];   // P tile, [k][m]
    __shared__ float Bs[16][97];   // V tile, [k][n]

    const int z = blockIdx.z;
    const int b = z / H;
    const int h = z - b * H;
    const float* Pz = S + (size_t)z * NTOK * NTOK;
    const float* Vz = V + (size_t)z * NTOK * D;

    const int tid = threadIdx.x;
    const int tx = tid & 15;
    const int ty = tid >> 4;
    const int row0 = blockIdx.y * 64;

    float acc[4][6];
#pragma unroll
    for (int i = 0; i < 4; i++)
#pragma unroll
        for (int j = 0; j < 6; j++) acc[i][j] = 0.f;

    const int kk = tid & 15;
    const int mm = tid >> 4;

    for (int k0 = 0; k0 < NTOK; k0 += 16) {
#pragma unroll
        for (int s = 0; s < 4; s++)
            As[kk][mm + s * 16] = Pz[(size_t)(row0 + mm + s * 16) * NTOK + k0 + kk];
#pragma unroll
        for (int s = 0; s < 6; s++) {
            const int idx = tid + s * 256;      // 0..1535
            const int bk = idx / D;             // 0..15
            const int bn = idx - bk * D;        // 0..95
            Bs[bk][bn] = Vz[(size_t)(k0 + bk) * D + bn];
        }
        __syncthreads();
#pragma unroll
        for (int k = 0; k < 16; k++) {
            float a[4], bb[6];
#pragma unroll
            for (int i = 0; i < 4; i++) a[i] = As[k][ty + i * 16];
#pragma unroll
            for (int j = 0; j < 6; j++) bb[j] = Bs[k][tx + j * 16];
#pragma unroll
            for (int i = 0; i < 4; i++)
#pragma unroll
                for (int j = 0; j < 6; j++) acc[i][j] += a[i] * bb[j];
        }
        __syncthreads();
    }

#pragma unroll
    for (int i = 0; i < 4; i++) {
        const int m = row0 + ty + i * 16;
#pragma unroll
        for (int j = 0; j < 6; j++) {
            const int d = tx + j * 16;
            A[((size_t)b * NTOK + m) * E + h * D + d] = acc[i][j];
        }
    }
}

// ---------------------------------------------------------------------------
extern "C" void kernel_launch(void* const* d_in, const int* in_sizes, int n_in,
                              void* d_out, int out_size) {
    const float* mammo = (const float*)d_in[0];
    const float* patho = (const float*)d_in[1];
    const float* q_w = (const float*)d_in[2];
    const float* q_b = (const float*)d_in[3];
    const float* k_w = (const float*)d_in[4];
    const float* k_b = (const float*)d_in[5];
    const float* v_w = (const float*)d_in[6];
    const float* v_b = (const float*)d_in[7];
    const float* o_w = (const float*)d_in[8];
    const float* o_b = (const float*)d_in[9];

    float* out_attended = (float*)d_out;                        // [B, N_m, E]
    float* out_attn_avg = (float*)d_out + (size_t)B * NTOK * E; // [B, N_m, N_p]

    float *Qp, *Kp, *Vp, *Sp, *Ap;
    cudaGetSymbolAddress((void**)&Qp, g_Q);
    cudaGetSymbolAddress((void**)&Kp, g_K);
    cudaGetSymbolAddress((void**)&Vp, g_V);
    cudaGetSymbolAddress((void**)&Sp, g_S);
    cudaGetSymbolAddress((void**)&Ap, g_A);

    const dim3 lin_grid(E / 64, MROWS / 64);   // (12, 128)
    linear_kernel<1><<<lin_grid, 256>>>(mammo, q_w, q_b, Qp);
    linear_kernel<1><<<lin_grid, 256>>>(patho, k_w, k_b, Kp);
    linear_kernel<1><<<lin_grid, 256>>>(patho, v_w, v_b, Vp);

    const float scale = 1.0f / sqrtf((float)D);
    scores_kernel<<<dim3(NTOK / 64, NTOK / 64, BHM), 256>>>(Qp, Kp, Sp, scale);

    softmax_kernel<<<BHM * NTOK, 256>>>(Sp);

    avg_kernel<<<B * NTOK, 256>>>(Sp, out_attn_avg);

    pv_kernel<<<dim3(1, NTOK / 64, BHM), 256>>>(Sp, Vp, Ap);

    linear_kernel<0><<<lin_grid, 256>>>(Ap, o_w, o_b, out_attended);
}

// round 2
// speedup vs baseline: 1.6458x; 1.6458x over previous
#include <cuda_runtime.h>
#include <math.h>

// Problem constants
#define B 8
#define NTOK 1024
#define E 768
#define H 8
#define D 96
#define BHM (B * H)
#define MROWS (B * NTOK)

// ---------------- device scratch (no allocations allowed) ----------------
__device__ float g_Q[B * H * NTOK * D];
__device__ float g_K[B * H * NTOK * D];
__device__ float g_V[B * H * NTOK * D];
__device__ float g_S[(size_t)BHM * NTOK * NTOK];   // 256 MB scores -> probs
__device__ float g_A[B * NTOK * E];

// ---------------------------------------------------------------------------
// Linear: C[M,768] = X[M,768] @ W[768,768]^T + bias
// 128x128 tile, BK=16, 256 threads, 8x8 per thread, double-buffered smem.
// QKV=1: scatter to [b,h,m,d]; QKV=0: row-major.
// ---------------------------------------------------------------------------
template <int QKV>
__launch_bounds__(256)
__global__ void linear128(const float* __restrict__ X,
                          const float* __restrict__ W,
                          const float* __restrict__ bias,
                          float* __restrict__ out) {
    __shared__ float As[2][16][132];
    __shared__ float Bs[2][16][132];

    const int tid = threadIdx.x;
    const int tx = tid & 15, ty = tid >> 4;
    const int row0 = blockIdx.y * 128, col0 = blockIdx.x * 128;
    const int lr = tid >> 2;          // 0..63
    const int lk = (tid & 3) * 4;     // 0,4,8,12

    float acc[8][8];
#pragma unroll
    for (int i = 0; i < 8; i++)
#pragma unroll
        for (int j = 0; j < 8; j++) acc[i][j] = 0.f;

    // initial tile
    {
        const float4 a0 = *(const float4*)&X[(size_t)(row0 + lr) * E + lk];
        const float4 a1 = *(const float4*)&X[(size_t)(row0 + lr + 64) * E + lk];
        const float4 b0 = *(const float4*)&W[(size_t)(col0 + lr) * E + lk];
        const float4 b1 = *(const float4*)&W[(size_t)(col0 + lr + 64) * E + lk];
        As[0][lk + 0][lr] = a0.x; As[0][lk + 1][lr] = a0.y; As[0][lk + 2][lr] = a0.z; As[0][lk + 3][lr] = a0.w;
        As[0][lk + 0][lr + 64] = a1.x; As[0][lk + 1][lr + 64] = a1.y; As[0][lk + 2][lr + 64] = a1.z; As[0][lk + 3][lr + 64] = a1.w;
        Bs[0][lk + 0][lr] = b0.x; Bs[0][lk + 1][lr] = b0.y; Bs[0][lk + 2][lr] = b0.z; Bs[0][lk + 3][lr] = b0.w;
        Bs[0][lk + 0][lr + 64] = b1.x; Bs[0][lk + 1][lr + 64] = b1.y; Bs[0][lk + 2][lr + 64] = b1.z; Bs[0][lk + 3][lr + 64] = b1.w;
    }
    __syncthreads();

    int buf = 0;
    const int KT = E / 16;   // 48
    for (int kt = 0; kt < KT; ++kt) {
        float4 a0, a1, b0, b1;
        if (kt + 1 < KT) {
            const int k0 = (kt + 1) * 16;
            a0 = *(const float4*)&X[(size_t)(row0 + lr) * E + k0 + lk];
            a1 = *(const float4*)&X[(size_t)(row0 + lr + 64) * E + k0 + lk];
            b0 = *(const float4*)&W[(size_t)(col0 + lr) * E + k0 + lk];
            b1 = *(const float4*)&W[(size_t)(col0 + lr + 64) * E + k0 + lk];
        }
#pragma unroll
        for (int k = 0; k < 16; ++k) {
            float a[8], bb[8];
            *(float4*)&a[0] = *(const float4*)&As[buf][k][ty * 4];
            *(float4*)&a[4] = *(const float4*)&As[buf][k][ty * 4 + 64];
            *(float4*)&bb[0] = *(const float4*)&Bs[buf][k][tx * 4];
            *(float4*)&bb[4] = *(const float4*)&Bs[buf][k][tx * 4 + 64];
#pragma unroll
            for (int i = 0; i < 8; i++)
#pragma unroll
                for (int j = 0; j < 8; j++) acc[i][j] += a[i] * bb[j];
        }
        if (kt + 1 < KT) {
            const int nb = buf ^ 1;
            As[nb][lk + 0][lr] = a0.x; As[nb][lk + 1][lr] = a0.y; As[nb][lk + 2][lr] = a0.z; As[nb][lk + 3][lr] = a0.w;
            As[nb][lk + 0][lr + 64] = a1.x; As[nb][lk + 1][lr + 64] = a1.y; As[nb][lk + 2][lr + 64] = a1.z; As[nb][lk + 3][lr + 64] = a1.w;
            Bs[nb][lk + 0][lr] = b0.x; Bs[nb][lk + 1][lr] = b0.y; Bs[nb][lk + 2][lr] = b0.z; Bs[nb][lk + 3][lr] = b0.w;
            Bs[nb][lk + 0][lr + 64] = b1.x; Bs[nb][lk + 1][lr + 64] = b1.y; Bs[nb][lk + 2][lr + 64] = b1.z; Bs[nb][lk + 3][lr + 64] = b1.w;
            buf = nb;
        }
        __syncthreads();
    }

#pragma unroll
    for (int ih = 0; ih < 2; ih++) {
#pragma unroll
        for (int i = 0; i < 4; i++) {
            const int r = row0 + ih * 64 + ty * 4 + i;
#pragma unroll
            for (int jh = 0; jh < 2; jh++) {
                const int c = col0 + jh * 64 + tx * 4;
                float4 v;
                v.x = acc[ih * 4 + i][jh * 4 + 0] + bias[c + 0];
                v.y = acc[ih * 4 + i][jh * 4 + 1] + bias[c + 1];
                v.z = acc[ih * 4 + i][jh * 4 + 2] + bias[c + 2];
                v.w = acc[ih * 4 + i][jh * 4 + 3] + bias[c + 3];
                if (QKV) {
                    const int bb_ = r >> 10, m = r & 1023;
                    const int h = c / D, d = c - h * D;
                    *(float4*)&out[(((size_t)(bb_ * H + h)) * NTOK + m) * D + d] = v;
                } else {
                    *(float4*)&out[(size_t)r * E + c] = v;
                }
            }
        }
    }
}

// ---------------------------------------------------------------------------
// Scores: per z: S[m,p] = scale * Q[z] @ K[z]^T  (both [1024,96] K-contiguous)
// 128x128 tile, BK=16, KT=6, 8x8 per thread.
// ---------------------------------------------------------------------------
__launch_bounds__(256)
__global__ void scores128(const float* __restrict__ Q,
                          const float* __restrict__ K,
                          float* __restrict__ S, float scale) {
    __shared__ float As[2][16][132];
    __shared__ float Bs[2][16][132];

    const int z = blockIdx.z;
    const float* Qz = Q + (size_t)z * NTOK * D;
    const float* Kz = K + (size_t)z * NTOK * D;
    float* Sz = S + (size_t)z * NTOK * NTOK;

    const int tid = threadIdx.x;
    const int tx = tid & 15, ty = tid >> 4;
    const int row0 = blockIdx.y * 128, col0 = blockIdx.x * 128;
    const int lr = tid >> 2;
    const int lk = (tid & 3) * 4;

    float acc[8][8];
#pragma unroll
    for (int i = 0; i < 8; i++)
#pragma unroll
        for (int j = 0; j < 8; j++) acc[i][j] = 0.f;

    {
        const float4 a0 = *(const float4*)&Qz[(size_t)(row0 + lr) * D + lk];
        const float4 a1 = *(const float4*)&Qz[(size_t)(row0 + lr + 64) * D + lk];
        const float4 b0 = *(const float4*)&Kz[(size_t)(col0 + lr) * D + lk];
        const float4 b1 = *(const float4*)&Kz[(size_t)(col0 + lr + 64) * D + lk];
        As[0][lk + 0][lr] = a0.x; As[0][lk + 1][lr] = a0.y; As[0][lk + 2][lr] = a0.z; As[0][lk + 3][lr] = a0.w;
        As[0][lk + 0][lr + 64] = a1.x; As[0][lk + 1][lr + 64] = a1.y; As[0][lk + 2][lr + 64] = a1.z; As[0][lk + 3][lr + 64] = a1.w;
        Bs[0][lk + 0][lr] = b0.x; Bs[0][lk + 1][lr] = b0.y; Bs[0][lk + 2][lr] = b0.z; Bs[0][lk + 3][lr] = b0.w;
        Bs[0][lk + 0][lr + 64] = b1.x; Bs[0][lk + 1][lr + 64] = b1.y; Bs[0][lk + 2][lr + 64] = b1.z; Bs[0][lk + 3][lr + 64] = b1.w;
    }
    __syncthreads();

    int buf = 0;
    const int KT = D / 16;   // 6
    for (int kt = 0; kt < KT; ++kt) {
        float4 a0, a1, b0, b1;
        if (kt + 1 < KT) {
            const int k0 = (kt + 1) * 16;
            a0 = *(const float4*)&Qz[(size_t)(row0 + lr) * D + k0 + lk];
            a1 = *(const float4*)&Qz[(size_t)(row0 + lr + 64) * D + k0 + lk];
            b0 = *(const float4*)&Kz[(size_t)(col0 + lr) * D + k0 + lk];
            b1 = *(const float4*)&Kz[(size_t)(col0 + lr + 64) * D + k0 + lk];
        }
#pragma unroll
        for (int k = 0; k < 16; ++k) {
            float a[8], bb[8];
            *(float4*)&a[0] = *(const float4*)&As[buf][k][ty * 4];
            *(float4*)&a[4] = *(const float4*)&As[buf][k][ty * 4 + 64];
            *(float4*)&bb[0] = *(const float4*)&Bs[buf][k][tx * 4];
            *(float4*)&bb[4] = *(const float4*)&Bs[buf][k][tx * 4 + 64];
#pragma unroll
            for (int i = 0; i < 8; i++)
#pragma unroll
                for (int j = 0; j < 8; j++) acc[i][j] += a[i] * bb[j];
        }
        if (kt + 1 < KT) {
            const int nb = buf ^ 1;
            As[nb][lk + 0][lr] = a0.x; As[nb][lk + 1][lr] = a0.y; As[nb][lk + 2][lr] = a0.z; As[nb][lk + 3][lr] = a0.w;
            As[nb][lk + 0][lr + 64] = a1.x; As[nb][lk + 1][lr + 64] = a1.y; As[nb][lk + 2][lr + 64] = a1.z; As[nb][lk + 3][lr + 64] = a1.w;
            Bs[nb][lk + 0][lr] = b0.x; Bs[nb][lk + 1][lr] = b0.y; Bs[nb][lk + 2][lr] = b0.z; Bs[nb][lk + 3][lr] = b0.w;
            Bs[nb][lk + 0][lr + 64] = b1.x; Bs[nb][lk + 1][lr + 64] = b1.y; Bs[nb][lk + 2][lr + 64] = b1.z; Bs[nb][lk + 3][lr + 64] = b1.w;
            buf = nb;
        }
        __syncthreads();
    }

#pragma unroll
    for (int ih = 0; ih < 2; ih++) {
#pragma unroll
        for (int i = 0; i < 4; i++) {
            const int m = row0 + ih * 64 + ty * 4 + i;
#pragma unroll
            for (int jh = 0; jh < 2; jh++) {
                const int p = col0 + jh * 64 + tx * 4;
                float4 v;
                v.x = acc[ih * 4 + i][jh * 4 + 0] * scale;
                v.y = acc[ih * 4 + i][jh * 4 + 1] * scale;
                v.z = acc[ih * 4 + i][jh * 4 + 2] * scale;
                v.w = acc[ih * 4 + i][jh * 4 + 3] * scale;
                *(float4*)&Sz[(size_t)m * NTOK + p] = v;
            }
        }
    }
}

// ---------------------------------------------------------------------------
// Fused softmax (in place) + head-average. One block per (b,m), warp per head.
// ---------------------------------------------------------------------------
__launch_bounds__(256)
__global__ void softmax_avg(float* __restrict__ S, float* __restrict__ avg_out) {
    __shared__ float sm[8][1024];
    const int bm = blockIdx.x;
    const int b = bm >> 10, m = bm & 1023;
    const int w = threadIdx.x >> 5, lane = threadIdx.x & 31;

    float4* row = (float4*)(S + (((size_t)(b * H + w)) * NTOK + m) * NTOK);
    float4 x[8];
    float mx = -INFINITY;
#pragma unroll
    for (int j = 0; j < 8; j++) {
        x[j] = row[lane + j * 32];
        mx = fmaxf(mx, fmaxf(fmaxf(x[j].x, x[j].y), fmaxf(x[j].z, x[j].w)));
    }
#pragma unroll
    for (int o = 16; o > 0; o >>= 1) mx = fmaxf(mx, __shfl_xor_sync(0xffffffffu, mx, o));

    float sum = 0.f;
#pragma unroll
    for (int j = 0; j < 8; j++) {
        x[j].x = __expf(x[j].x - mx); x[j].y = __expf(x[j].y - mx);
        x[j].z = __expf(x[j].z - mx); x[j].w = __expf(x[j].w - mx);
        sum += x[j].x + x[j].y + x[j].z + x[j].w;
    }
#pragma unroll
    for (int o = 16; o > 0; o >>= 1) sum += __shfl_xor_sync(0xffffffffu, sum, o);
    const float inv = 1.f / sum;

    float4* smrow = (float4*)sm[w];
#pragma unroll
    for (int j = 0; j < 8; j++) {
        x[j].x *= inv; x[j].y *= inv; x[j].z *= inv; x[j].w *= inv;
        row[lane + j * 32] = x[j];
        smrow[lane + j * 32] = x[j];
    }
    __syncthreads();

    const int t = threadIdx.x;
    float4 acc = make_float4(0.f, 0.f, 0.f, 0.f);
#pragma unroll
    for (int h = 0; h < 8; h++) {
        const float4 v = ((float4*)sm[h])[t];
        acc.x += v.x; acc.y += v.y; acc.z += v.z; acc.w += v.w;
    }
    acc.x *= 0.125f; acc.y *= 0.125f; acc.z *= 0.125f; acc.w *= 0.125f;
    ((float4*)(avg_out + (size_t)bm * NTOK))[t] = acc;
}

// ---------------------------------------------------------------------------
// PV: per z: C[1024,96] = P[1024,1024] @ V[1024,96]
// 128x96 tile, BK=16, KT=64, 8x6 per thread, double-buffered.
// ---------------------------------------------------------------------------
__launch_bounds__(256)
__global__ void pv128(const float* __restrict__ S,
                      const float* __restrict__ V,
                      float* __restrict__ A) {
    __shared__ float Ps[2][16][132];
    __shared__ float Vs[2][16][100];

    const int z = blockIdx.z;
    const int b = z >> 3, h = z & 7;
    const float* Pz = S + (size_t)z * NTOK * NTOK;
    const float* Vz = V + (size_t)z * NTOK * D;

    const int tid = threadIdx.x;
    const int tx = tid & 15, ty = tid >> 4;
    const int row0 = blockIdx.y * 128;
    const int lr = tid >> 2;
    const int lk = (tid & 3) * 4;

    float acc[8][6];
#pragma unroll
    for (int i = 0; i < 8; i++)
#pragma unroll
        for (int j = 0; j < 6; j++) acc[i][j] = 0.f;

    {
        const float4 a0 = *(const float4*)&Pz[(size_t)(row0 + lr) * NTOK + lk];
        const float4 a1 = *(const float4*)&Pz[(size_t)(row0 + lr + 64) * NTOK + lk];
        Ps[0][lk + 0][lr] = a0.x; Ps[0][lk + 1][lr] = a0.y; Ps[0][lk + 2][lr] = a0.z; Ps[0][lk + 3][lr] = a0.w;
        Ps[0][lk + 0][lr + 64] = a1.x; Ps[0][lk + 1][lr + 64] = a1.y; Ps[0][lk + 2][lr + 64] = a1.z; Ps[0][lk + 3][lr + 64] = a1.w;
#pragma unroll
        for (int s = 0; s < 6; s++) {
            const int idx = tid + s * 256;
            const int r = idx / D, c = idx - r * D;
            Vs[0][r][c] = Vz[(size_t)r * D + c];
        }
    }
    __syncthreads();

    int buf = 0;
    const int KT = NTOK / 16;  // 64
    for (int kt = 0; kt < KT; ++kt) {
        float4 a0, a1;
        float vv[6];
        if (kt + 1 < KT) {
            const int k0 = (kt + 1) * 16;
            a0 = *(const float4*)&Pz[(size_t)(row0 + lr) * NTOK + k0 + lk];
            a1 = *(const float4*)&Pz[(size_t)(row0 + lr + 64) * NTOK + k0 + lk];
#pragma unroll
            for (int s = 0; s < 6; s++) {
                const int idx = tid + s * 256;
                const int r = idx / D, c = idx - r * D;
                vv[s] = Vz[(size_t)(k0 + r) * D + c];
            }
        }
#pragma unroll
        for (int k = 0; k < 16; ++k) {
            float a[8], bb[6];
            *(float4*)&a[0] = *(const float4*)&Ps[buf][k][ty * 4];
            *(float4*)&a[4] = *(const float4*)&Ps[buf][k][ty * 4 + 64];
#pragma unroll
            for (int j = 0; j < 6; j++) bb[j] = Vs[buf][k][tx * 6 + j];
#pragma unroll
            for (int i = 0; i < 8; i++)
#pragma unroll
                for (int j = 0; j < 6; j++) acc[i][j] += a[i] * bb[j];
        }
        if (kt + 1 < KT) {
            const int nb = buf ^ 1;
            Ps[nb][lk + 0][lr] = a0.x; Ps[nb][lk + 1][lr] = a0.y; Ps[nb][lk + 2][lr] = a0.z; Ps[nb][lk + 3][lr] = a0.w;
            Ps[nb][lk + 0][lr + 64] = a1.x; Ps[nb][lk + 1][lr + 64] = a1.y; Ps[nb][lk + 2][lr + 64] = a1.z; Ps[nb][lk + 3][lr + 64] = a1.w;
#pragma unroll
            for (int s = 0; s < 6; s++) {
                const int idx = tid + s * 256;
                const int r = idx / D, c = idx - r * D;
                Vs[nb][r][c] = vv[s];
            }
            buf = nb;
        }
        __syncthreads();
    }

#pragma unroll
    for (int ih = 0; ih < 2; ih++) {
#pragma unroll
        for (int i = 0; i < 4; i++) {
            const int m = row0 + ih * 64 + ty * 4 + i;
            float* dst = &A[((size_t)b * NTOK + m) * E + h * D + tx * 6];
#pragma unroll
            for (int j = 0; j < 6; j++) dst[j] = acc[ih * 4 + i][j];
        }
    }
}

// ---------------------------------------------------------------------------
extern "C" void kernel_launch(void* const* d_in, const int* in_sizes, int n_in,
                              void* d_out, int out_size) {
    const float* mammo = (const float*)d_in[0];
    const float* patho = (const float*)d_in[1];
    const float* q_w = (const float*)d_in[2];
    const float* q_b = (const float*)d_in[3];
    const float* k_w = (const float*)d_in[4];
    const float* k_b = (const float*)d_in[5];
    const float* v_w = (const float*)d_in[6];
    const float* v_b = (const float*)d_in[7];
    const float* o_w = (const float*)d_in[8];
    const float* o_b = (const float*)d_in[9];

    float* out_attended = (float*)d_out;
    float* out_attn_avg = (float*)d_out + (size_t)B * NTOK * E;

    float *Qp, *Kp, *Vp, *Sp, *Ap;
    cudaGetSymbolAddress((void**)&Qp, g_Q);
    cudaGetSymbolAddress((void**)&Kp, g_K);
    cudaGetSymbolAddress((void**)&Vp, g_V);
    cudaGetSymbolAddress((void**)&Sp, g_S);
    cudaGetSymbolAddress((void**)&Ap, g_A);

    const dim3 lin_grid(E / 128, MROWS / 128);   // (6, 64)
    linear128<1><<<lin_grid, 256>>>(mammo, q_w, q_b, Qp);
    linear128<1><<<lin_grid, 256>>>(patho, k_w, k_b, Kp);
    linear128<1><<<lin_grid, 256>>>(patho, v_w, v_b, Vp);

    const float scale = 1.0f / sqrtf((float)D);
    scores128<<<dim3(NTOK / 128, NTOK / 128, BHM), 256>>>(Qp, Kp, Sp, scale);

    softmax_avg<<<B * NTOK, 256>>>(Sp, out_attn_avg);

    pv128<<<dim3(1, NTOK / 128, BHM), 256>>>(Sp, Vp, Ap);

    linear128<0><<<lin_grid, 256>>>(Ap, o_w, o_b, out_attended);
}

// round 3
// speedup vs baseline: 3.3641x; 2.0440x over previous
#include <cuda_runtime.h>
#include <math.h>
#include <stdint.h>

// Problem constants
#define B 8
#define NTOK 1024
#define E 768
#define H 8
#define D 96
#define BHM (B * H)
#define MROWS (B * NTOK)

// ---------------- device scratch (no allocations allowed) ----------------
__device__ float g_Q[B * H * NTOK * D];
__device__ float g_K[B * H * NTOK * D];
__device__ float g_V[B * H * NTOK * D];
__device__ float g_S[(size_t)BHM * NTOK * NTOK];   // 256 MB scores -> probs
__device__ float g_A[B * NTOK * E];

// ---------------------------------------------------------------------------
__device__ __forceinline__ float to_tf32(float x) {
    float r;
    asm("cvt.rna.tf32.f32 %0, %1;" : "=f"(r) : "f"(x));
    return r;
}

__device__ __forceinline__ void mma_tf32(float4& c, const uint32_t a[4], const uint32_t b[2]) {
    asm volatile(
        "mma.sync.aligned.m16n8k8.row.col.f32.tf32.tf32.f32 "
        "{%0,%1,%2,%3}, {%4,%5,%6,%7}, {%8,%9}, {%0,%1,%2,%3};"
        : "+f"(c.x), "+f"(c.y), "+f"(c.z), "+f"(c.w)
        : "r"(a[0]), "r"(a[1]), "r"(a[2]), "r"(a[3]), "r"(b[0]), "r"(b[1]));
}

// Compute one BK=16 buffer: NT n-tiles of 8, 4 m-tiles of 16.
// As: [128][20] (m,k) ; Bs: [BN][20] (n,k).
template <int NT>
__device__ __forceinline__ void mma_buffer(const float (*As)[20], const float (*Bs)[20],
                                           float4 acc[4][NT],
                                           int warp_m, int warp_n, int g, int t) {
#pragma unroll
    for (int ks = 0; ks < 2; ks++) {
        const int kb = ks * 8;
        uint32_t af[4][4];
#pragma unroll
        for (int mt = 0; mt < 4; mt++) {
            const int r = warp_m * 64 + mt * 16;
            af[mt][0] = __float_as_uint(As[r + g][kb + t]);
            af[mt][1] = __float_as_uint(As[r + g + 8][kb + t]);
            af[mt][2] = __float_as_uint(As[r + g][kb + t + 4]);
            af[mt][3] = __float_as_uint(As[r + g + 8][kb + t + 4]);
        }
        uint32_t bf[NT][2];
#pragma unroll
        for (int nt = 0; nt < NT; nt++) {
            const int cbase = warp_n * (NT * 8) + nt * 8;
            bf[nt][0] = __float_as_uint(Bs[cbase + g][kb + t]);
            bf[nt][1] = __float_as_uint(Bs[cbase + g][kb + t + 4]);
        }
#pragma unroll
        for (int mt = 0; mt < 4; mt++)
#pragma unroll
            for (int nt = 0; nt < NT; nt++) mma_tf32(acc[mt][nt], af[mt], bf[nt]);
    }
}

// ---------------------------------------------------------------------------
// Linear: C[M,768] = X[M,768] @ W[768,768]^T + bias, tf32 tensor cores.
// 128x128 block, BK=16, 256 threads (8 warps 2x4), warp tile 64x32.
// ---------------------------------------------------------------------------
template <int QKV>
__launch_bounds__(256)
__global__ void linear_tf32(const float* __restrict__ X,
                            const float* __restrict__ W,
                            const float* __restrict__ bias,
                            float* __restrict__ out) {
    __shared__ float As[2][128][20];
    __shared__ float Bs[2][128][20];

    const int tid = threadIdx.x;
    const int lane = tid & 31;
    const int w = tid >> 5;
    const int warp_m = w & 1, warp_n = w >> 1;
    const int g = lane >> 2, t = lane & 3;
    const int row0 = blockIdx.y * 128, col0 = blockIdx.x * 128;

    const int arow0 = tid >> 2;            // f4id mapping, s adds 64 rows
    const int akq = (tid & 3) * 4;

    float4 acc[4][4];
#pragma unroll
    for (int i = 0; i < 4; i++)
#pragma unroll
        for (int j = 0; j < 4; j++) acc[i][j] = make_float4(0.f, 0.f, 0.f, 0.f);

    // initial fill
#pragma unroll
    for (int s = 0; s < 2; s++) {
        const int r = arow0 + s * 64;
        const float4 a = *(const float4*)&X[(size_t)(row0 + r) * E + akq];
        const float4 b = *(const float4*)&W[(size_t)(col0 + r) * E + akq];
        As[0][r][akq + 0] = to_tf32(a.x); As[0][r][akq + 1] = to_tf32(a.y);
        As[0][r][akq + 2] = to_tf32(a.z); As[0][r][akq + 3] = to_tf32(a.w);
        Bs[0][r][akq + 0] = to_tf32(b.x); Bs[0][r][akq + 1] = to_tf32(b.y);
        Bs[0][r][akq + 2] = to_tf32(b.z); Bs[0][r][akq + 3] = to_tf32(b.w);
    }
    __syncthreads();

    int buf = 0;
    const int KT = E / 16;   // 48
    for (int kt = 0; kt < KT; kt++) {
        float4 pa[2], pb[2];
        if (kt + 1 < KT) {
            const int k0 = (kt + 1) * 16;
#pragma unroll
            for (int s = 0; s < 2; s++) {
                const int r = arow0 + s * 64;
                pa[s] = *(const float4*)&X[(size_t)(row0 + r) * E + k0 + akq];
                pb[s] = *(const float4*)&W[(size_t)(col0 + r) * E + k0 + akq];
            }
        }
        mma_buffer<4>(As[buf], Bs[buf], acc, warp_m, warp_n, g, t);
        if (kt + 1 < KT) {
            const int nb = buf ^ 1;
#pragma unroll
            for (int s = 0; s < 2; s++) {
                const int r = arow0 + s * 64;
                As[nb][r][akq + 0] = to_tf32(pa[s].x); As[nb][r][akq + 1] = to_tf32(pa[s].y);
                As[nb][r][akq + 2] = to_tf32(pa[s].z); As[nb][r][akq + 3] = to_tf32(pa[s].w);
                Bs[nb][r][akq + 0] = to_tf32(pb[s].x); Bs[nb][r][akq + 1] = to_tf32(pb[s].y);
                Bs[nb][r][akq + 2] = to_tf32(pb[s].z); Bs[nb][r][akq + 3] = to_tf32(pb[s].w);
            }
            buf = nb;
        }
        __syncthreads();
    }

    // epilogue
#pragma unroll
    for (int mt = 0; mt < 4; mt++) {
        const int r = row0 + warp_m * 64 + mt * 16 + g;
#pragma unroll
        for (int nt = 0; nt < 4; nt++) {
            const int c = col0 + warp_n * 32 + nt * 8 + 2 * t;
            const float bx = bias[c], by = bias[c + 1];
            float2 v0 = make_float2(acc[mt][nt].x + bx, acc[mt][nt].y + by);
            float2 v1 = make_float2(acc[mt][nt].z + bx, acc[mt][nt].w + by);
            if (QKV) {
                const int bb_ = r >> 10, m = r & 1023;
                const int hh = c / D, d = c - hh * D;
                float* base = &g_Q[0];  // unused; silence
                (void)base;
                const size_t o0 = (((size_t)(bb_ * H + hh)) * NTOK + m) * D + d;
                const int bb2 = (r + 8) >> 10, m2 = (r + 8) & 1023;
                const size_t o1 = (((size_t)(bb2 * H + hh)) * NTOK + m2) * D + d;
                *(float2*)&out[o0] = v0;
                *(float2*)&out[o1] = v1;
            } else {
                *(float2*)&out[(size_t)r * E + c] = v0;
                *(float2*)&out[(size_t)(r + 8) * E + c] = v1;
            }
        }
    }
}

// ---------------------------------------------------------------------------
// Scores: per z: S = scale * Q @ K^T, Q/K [1024,96] k-contiguous. tf32.
// ---------------------------------------------------------------------------
__launch_bounds__(256)
__global__ void scores_tf32(const float* __restrict__ Q,
                            const float* __restrict__ K,
                            float* __restrict__ S, float scale) {
    __shared__ float As[2][128][20];
    __shared__ float Bs[2][128][20];

    const int z = blockIdx.z;
    const float* Qz = Q + (size_t)z * NTOK * D;
    const float* Kz = K + (size_t)z * NTOK * D;
    float* Sz = S + (size_t)z * NTOK * NTOK;

    const int tid = threadIdx.x;
    const int lane = tid & 31;
    const int w = tid >> 5;
    const int warp_m = w & 1, warp_n = w >> 1;
    const int g = lane >> 2, t = lane & 3;
    const int row0 = blockIdx.y * 128, col0 = blockIdx.x * 128;

    const int arow0 = tid >> 2;
    const int akq = (tid & 3) * 4;

    float4 acc[4][4];
#pragma unroll
    for (int i = 0; i < 4; i++)
#pragma unroll
        for (int j = 0; j < 4; j++) acc[i][j] = make_float4(0.f, 0.f, 0.f, 0.f);

#pragma unroll
    for (int s = 0; s < 2; s++) {
        const int r = arow0 + s * 64;
        const float4 a = *(const float4*)&Qz[(size_t)(row0 + r) * D + akq];
        const float4 b = *(const float4*)&Kz[(size_t)(col0 + r) * D + akq];
        As[0][r][akq + 0] = to_tf32(a.x); As[0][r][akq + 1] = to_tf32(a.y);
        As[0][r][akq + 2] = to_tf32(a.z); As[0][r][akq + 3] = to_tf32(a.w);
        Bs[0][r][akq + 0] = to_tf32(b.x); Bs[0][r][akq + 1] = to_tf32(b.y);
        Bs[0][r][akq + 2] = to_tf32(b.z); Bs[0][r][akq + 3] = to_tf32(b.w);
    }
    __syncthreads();

    int buf = 0;
    const int KT = D / 16;   // 6
    for (int kt = 0; kt < KT; kt++) {
        float4 pa[2], pb[2];
        if (kt + 1 < KT) {
            const int k0 = (kt + 1) * 16;
#pragma unroll
            for (int s = 0; s < 2; s++) {
                const int r = arow0 + s * 64;
                pa[s] = *(const float4*)&Qz[(size_t)(row0 + r) * D + k0 + akq];
                pb[s] = *(const float4*)&Kz[(size_t)(col0 + r) * D + k0 + akq];
            }
        }
        mma_buffer<4>(As[buf], Bs[buf], acc, warp_m, warp_n, g, t);
        if (kt + 1 < KT) {
            const int nb = buf ^ 1;
#pragma unroll
            for (int s = 0; s < 2; s++) {
                const int r = arow0 + s * 64;
                As[nb][r][akq + 0] = to_tf32(pa[s].x); As[nb][r][akq + 1] = to_tf32(pa[s].y);
                As[nb][r][akq + 2] = to_tf32(pa[s].z); As[nb][r][akq + 3] = to_tf32(pa[s].w);
                Bs[nb][r][akq + 0] = to_tf32(pb[s].x); Bs[nb][r][akq + 1] = to_tf32(pb[s].y);
                Bs[nb][r][akq + 2] = to_tf32(pb[s].z); Bs[nb][r][akq + 3] = to_tf32(pb[s].w);
            }
            buf = nb;
        }
        __syncthreads();
    }

#pragma unroll
    for (int mt = 0; mt < 4; mt++) {
        const int m = row0 + warp_m * 64 + mt * 16 + g;
#pragma unroll
        for (int nt = 0; nt < 4; nt++) {
            const int p = col0 + warp_n * 32 + nt * 8 + 2 * t;
            float2 v0 = make_float2(acc[mt][nt].x * scale, acc[mt][nt].y * scale);
            float2 v1 = make_float2(acc[mt][nt].z * scale, acc[mt][nt].w * scale);
            *(float2*)&Sz[(size_t)m * NTOK + p] = v0;
            *(float2*)&Sz[(size_t)(m + 8) * NTOK + p] = v1;
        }
    }
}

// ---------------------------------------------------------------------------
// Fused softmax (in place) + head-average. One block per (b,m), warp per head.
// ---------------------------------------------------------------------------
__launch_bounds__(256)
__global__ void softmax_avg(float* __restrict__ S, float* __restrict__ avg_out) {
    __shared__ float sm[8][1024];
    const int bm = blockIdx.x;
    const int b = bm >> 10, m = bm & 1023;
    const int w = threadIdx.x >> 5, lane = threadIdx.x & 31;

    float4* row = (float4*)(S + (((size_t)(b * H + w)) * NTOK + m) * NTOK);
    float4 x[8];
    float mx = -INFINITY;
#pragma unroll
    for (int j = 0; j < 8; j++) {
        x[j] = row[lane + j * 32];
        mx = fmaxf(mx, fmaxf(fmaxf(x[j].x, x[j].y), fmaxf(x[j].z, x[j].w)));
    }
#pragma unroll
    for (int o = 16; o > 0; o >>= 1) mx = fmaxf(mx, __shfl_xor_sync(0xffffffffu, mx, o));

    float sum = 0.f;
#pragma unroll
    for (int j = 0; j < 8; j++) {
        x[j].x = __expf(x[j].x - mx); x[j].y = __expf(x[j].y - mx);
        x[j].z = __expf(x[j].z - mx); x[j].w = __expf(x[j].w - mx);
        sum += x[j].x + x[j].y + x[j].z + x[j].w;
    }
#pragma unroll
    for (int o = 16; o > 0; o >>= 1) sum += __shfl_xor_sync(0xffffffffu, sum, o);
    const float inv = 1.f / sum;

    float4* smrow = (float4*)sm[w];
#pragma unroll
    for (int j = 0; j < 8; j++) {
        x[j].x *= inv; x[j].y *= inv; x[j].z *= inv; x[j].w *= inv;
        row[lane + j * 32] = x[j];
        smrow[lane + j * 32] = x[j];
    }
    __syncthreads();

    const int tt = threadIdx.x;
    float4 acc = make_float4(0.f, 0.f, 0.f, 0.f);
#pragma unroll
    for (int h = 0; h < 8; h++) {
        const float4 v = ((float4*)sm[h])[tt];
        acc.x += v.x; acc.y += v.y; acc.z += v.z; acc.w += v.w;
    }
    acc.x *= 0.125f; acc.y *= 0.125f; acc.z *= 0.125f; acc.w *= 0.125f;
    ((float4*)(avg_out + (size_t)bm * NTOK))[tt] = acc;
}

// ---------------------------------------------------------------------------
// PV: per z: C[1024,96] = P[1024,1024] @ V[1024,96]. tf32 tensor cores.
// 128x96 block, warp tile 64x24 (NT=3), BK=16, V transposed into Bs[n][k].
// ---------------------------------------------------------------------------
__launch_bounds__(256)
__global__ void pv_tf32(const float* __restrict__ S,
                        const float* __restrict__ V,
                        float* __restrict__ A) {
    __shared__ float As[2][128][20];
    __shared__ float Bs[2][96][20];

    const int z = blockIdx.z;
    const int b = z >> 3, h = z & 7;
    const float* Pz = S + (size_t)z * NTOK * NTOK;
    const float* Vz = V + (size_t)z * NTOK * D;

    const int tid = threadIdx.x;
    const int lane = tid & 31;
    const int w = tid >> 5;
    const int warp_m = w & 1, warp_n = w >> 1;
    const int g = lane >> 2, t = lane & 3;
    const int row0 = blockIdx.y * 128;

    const int arow0 = tid >> 2;
    const int akq = (tid & 3) * 4;

    float4 acc[4][3];
#pragma unroll
    for (int i = 0; i < 4; i++)
#pragma unroll
        for (int j = 0; j < 3; j++) acc[i][j] = make_float4(0.f, 0.f, 0.f, 0.f);

    // initial fill
#pragma unroll
    for (int s = 0; s < 2; s++) {
        const int r = arow0 + s * 64;
        const float4 a = *(const float4*)&Pz[(size_t)(row0 + r) * NTOK + akq];
        As[0][r][akq + 0] = to_tf32(a.x); As[0][r][akq + 1] = to_tf32(a.y);
        As[0][r][akq + 2] = to_tf32(a.z); As[0][r][akq + 3] = to_tf32(a.w);
    }
#pragma unroll
    for (int s = 0; s < 6; s++) {
        const int idx = tid + s * 256;          // 0..1535
        const int k = idx / D;                  // 0..15
        const int n = idx - k * D;              // 0..95
        Bs[0][n][k] = to_tf32(Vz[(size_t)k * D + n]);
    }
    __syncthreads();

    int buf = 0;
    const int KT = NTOK / 16;  // 64
    for (int kt = 0; kt < KT; kt++) {
        float4 pa[2];
        float pv[6];
        if (kt + 1 < KT) {
            const int k0 = (kt + 1) * 16;
#pragma unroll
            for (int s = 0; s < 2; s++) {
                const int r = arow0 + s * 64;
                pa[s] = *(const float4*)&Pz[(size_t)(row0 + r) * NTOK + k0 + akq];
            }
#pragma unroll
            for (int s = 0; s < 6; s++) {
                const int idx = tid + s * 256;
                const int k = idx / D;
                const int n = idx - k * D;
                pv[s] = Vz[(size_t)(k0 + k) * D + n];
            }
        }
        mma_buffer<3>(As[buf], Bs[buf], acc, warp_m, warp_n, g, t);
        if (kt + 1 < KT) {
            const int nb = buf ^ 1;
#pragma unroll
            for (int s = 0; s < 2; s++) {
                const int r = arow0 + s * 64;
                As[nb][r][akq + 0] = to_tf32(pa[s].x); As[nb][r][akq + 1] = to_tf32(pa[s].y);
                As[nb][r][akq + 2] = to_tf32(pa[s].z); As[nb][r][akq + 3] = to_tf32(pa[s].w);
            }
#pragma unroll
            for (int s = 0; s < 6; s++) {
                const int idx = tid + s * 256;
                const int k = idx / D;
                const int n = idx - k * D;
                Bs[nb][n][k] = to_tf32(pv[s]);
            }
            buf = nb;
        }
        __syncthreads();
    }

#pragma unroll
    for (int mt = 0; mt < 4; mt++) {
        const int m = row0 + warp_m * 64 + mt * 16 + g;
#pragma unroll
        for (int nt = 0; nt < 3; nt++) {
            const int d = warp_n * 24 + nt * 8 + 2 * t;
            float2 v0 = make_float2(acc[mt][nt].x, acc[mt][nt].y);
            float2 v1 = make_float2(acc[mt][nt].z, acc[mt][nt].w);
            *(float2*)&A[((size_t)b * NTOK + m) * E + h * D + d] = v0;
            *(float2*)&A[((size_t)b * NTOK + m + 8) * E + h * D + d] = v1;
        }
    }
}

// ---------------------------------------------------------------------------
extern "C" void kernel_launch(void* const* d_in, const int* in_sizes, int n_in,
                              void* d_out, int out_size) {
    const float* mammo = (const float*)d_in[0];
    const float* patho = (const float*)d_in[1];
    const float* q_w = (const float*)d_in[2];
    const float* q_b = (const float*)d_in[3];
    const float* k_w = (const float*)d_in[4];
    const float* k_b = (const float*)d_in[5];
    const float* v_w = (const float*)d_in[6];
    const float* v_b = (const float*)d_in[7];
    const float* o_w = (const float*)d_in[8];
    const float* o_b = (const float*)d_in[9];

    float* out_attended = (float*)d_out;
    float* out_attn_avg = (float*)d_out + (size_t)B * NTOK * E;

    float *Qp, *Kp, *Vp, *Sp, *Ap;
    cudaGetSymbolAddress((void**)&Qp, g_Q);
    cudaGetSymbolAddress((void**)&Kp, g_K);
    cudaGetSymbolAddress((void**)&Vp, g_V);
    cudaGetSymbolAddress((void**)&Sp, g_S);
    cudaGetSymbolAddress((void**)&Ap, g_A);

    const dim3 lin_grid(E / 128, MROWS / 128);   // (6, 64)
    linear_tf32<1><<<lin_grid, 256>>>(mammo, q_w, q_b, Qp);
    linear_tf32<1><<<lin_grid, 256>>>(patho, k_w, k_b, Kp);
    linear_tf32<1><<<lin_grid, 256>>>(patho, v_w, v_b, Vp);

    const float scale = 1.0f / sqrtf((float)D);
    scores_tf32<<<dim3(NTOK / 128, NTOK / 128, BHM), 256>>>(Qp, Kp, Sp, scale);

    softmax_avg<<<B * NTOK, 256>>>(Sp, out_attn_avg);

    pv_tf32<<<dim3(1, NTOK / 128, BHM), 256>>>(Sp, Vp, Ap);

    linear_tf32<0><<<lin_grid, 256>>>(Ap, o_w, o_b, out_attended);
}

// round 5
// speedup vs baseline: 3.8479x; 1.1438x over previous
#include <cuda_runtime.h>
#include <cuda_fp16.h>
#include <math.h>
#include <stdint.h>

// Problem constants
#define B 8
#define NTOK 1024
#define E 768
#define H 8
#define D 96
#define BHM (B * H)
#define MROWS (B * NTOK)

// ---------------- device scratch (no allocations allowed) ----------------
__device__ __half g_Q[B * H * NTOK * D];                 // fp16 [b,h,m,d]
__device__ __half g_K[B * H * NTOK * D];
__device__ __half g_V[B * H * NTOK * D];
__device__ __half g_S[(size_t)BHM * NTOK * NTOK];        // 128 MB scores -> probs
__device__ float  g_A[B * NTOK * E];                     // attended pre-O (fp32)

// ---------------------------------------------------------------------------
__device__ __forceinline__ uint32_t pack_half2(__half lo, __half hi) {
    __half2 h = __halves2half2(lo, hi);
    uint32_t u;
    u = *reinterpret_cast<uint32_t*>(&h);
    return u;
}

__device__ __forceinline__ float to_tf32(float x) {
    float r;
    asm("cvt.rna.tf32.f32 %0, %1;" : "=f"(r) : "f"(x));
    return r;
}

__device__ __forceinline__ void mma_tf32(float4& c, const uint32_t a[4], const uint32_t b[2]) {
    asm volatile(
        "mma.sync.aligned.m16n8k8.row.col.f32.tf32.tf32.f32 "
        "{%0,%1,%2,%3}, {%4,%5,%6,%7}, {%8,%9}, {%0,%1,%2,%3};"
        : "+f"(c.x), "+f"(c.y), "+f"(c.z), "+f"(c.w)
        : "r"(a[0]), "r"(a[1]), "r"(a[2]), "r"(a[3]), "r"(b[0]), "r"(b[1]));
}

__device__ __forceinline__ void mma_f16(float4& c, const uint32_t a[4], const uint32_t b[2]) {
    asm volatile(
        "mma.sync.aligned.m16n8k16.row.col.f32.f16.f16.f32 "
        "{%0,%1,%2,%3}, {%4,%5,%6,%7}, {%8,%9}, {%0,%1,%2,%3};"
        : "+f"(c.x), "+f"(c.y), "+f"(c.z), "+f"(c.w)
        : "r"(a[0]), "r"(a[1]), "r"(a[2]), "r"(a[3]), "r"(b[0]), "r"(b[1]));
}

// tf32: one BK=16 buffer. As: [128][20] (m,k) floats; Bs: [BN][20] (n,k).
template <int NT>
__device__ __forceinline__ void mma_buffer(const float (*As)[20], const float (*Bs)[20],
                                           float4 acc[4][NT],
                                           int warp_m, int warp_n, int g, int t) {
#pragma unroll
    for (int ks = 0; ks < 2; ks++) {
        const int kb = ks * 8;
        uint32_t af[4][4];
#pragma unroll
        for (int mt = 0; mt < 4; mt++) {
            const int r = warp_m * 64 + mt * 16;
            af[mt][0] = __float_as_uint(As[r + g][kb + t]);
            af[mt][1] = __float_as_uint(As[r + g + 8][kb + t]);
            af[mt][2] = __float_as_uint(As[r + g][kb + t + 4]);
            af[mt][3] = __float_as_uint(As[r + g + 8][kb + t + 4]);
        }
        uint32_t bf[NT][2];
#pragma unroll
        for (int nt = 0; nt < NT; nt++) {
            const int cbase = warp_n * (NT * 8) + nt * 8;
            bf[nt][0] = __float_as_uint(Bs[cbase + g][kb + t]);
            bf[nt][1] = __float_as_uint(Bs[cbase + g][kb + t + 4]);
        }
#pragma unroll
        for (int mt = 0; mt < 4; mt++)
#pragma unroll
            for (int nt = 0; nt < NT; nt++) mma_tf32(acc[mt][nt], af[mt], bf[nt]);
    }
}

// fp16: one BK=32(halves) buffer. As: uint32 [128][20] (m, kpair); Bs: [BN][20].
template <int NT>
__device__ __forceinline__ void mma_buffer16(const uint32_t (*As)[20], const uint32_t (*Bs)[20],
                                             float4 acc[4][NT],
                                             int warp_m, int warp_n, int g, int t) {
#pragma unroll
    for (int ks = 0; ks < 2; ks++) {
        const int kc = ks * 8;
        uint32_t af[4][4];
#pragma unroll
        for (int mt = 0; mt < 4; mt++) {
            const int r = warp_m * 64 + mt * 16;
            af[mt][0] = As[r + g][kc + t];
            af[mt][1] = As[r + g + 8][kc + t];
            af[mt][2] = As[r + g][kc + t + 4];
            af[mt][3] = As[r + g + 8][kc + t + 4];
        }
        uint32_t bf[NT][2];
#pragma unroll
        for (int nt = 0; nt < NT; nt++) {
            const int cbase = warp_n * (NT * 8) + nt * 8;
            bf[nt][0] = Bs[cbase + g][kc + t];
            bf[nt][1] = Bs[cbase + g][kc + t + 4];
        }
#pragma unroll
        for (int mt = 0; mt < 4; mt++)
#pragma unroll
            for (int nt = 0; nt < NT; nt++) mma_f16(acc[mt][nt], af[mt], bf[nt]);
    }
}

// ---------------------------------------------------------------------------
// Linear: C[M,768] = X[M,768] @ W[768,768]^T + bias, tf32 tensor cores.
// QKV=1: write fp16 to [b,h,m,d]; QKV=0: write fp32 row-major.
// ---------------------------------------------------------------------------
template <int QKV>
__launch_bounds__(256)
__global__ void linear_tf32(const float* __restrict__ X,
                            const float* __restrict__ W,
                            const float* __restrict__ bias,
                            void* __restrict__ out_) {
    __shared__ float As[2][128][20];
    __shared__ float Bs[2][128][20];

    const int tid = threadIdx.x;
    const int lane = tid & 31;
    const int w = tid >> 5;
    const int warp_m = w & 1, warp_n = w >> 1;
    const int g = lane >> 2, t = lane & 3;
    const int row0 = blockIdx.y * 128, col0 = blockIdx.x * 128;

    const int arow0 = tid >> 2;
    const int akq = (tid & 3) * 4;

    float4 acc[4][4];
#pragma unroll
    for (int i = 0; i < 4; i++)
#pragma unroll
        for (int j = 0; j < 4; j++) acc[i][j] = make_float4(0.f, 0.f, 0.f, 0.f);

#pragma unroll
    for (int s = 0; s < 2; s++) {
        const int r = arow0 + s * 64;
        const float4 a = *(const float4*)&X[(size_t)(row0 + r) * E + akq];
        const float4 b = *(const float4*)&W[(size_t)(col0 + r) * E + akq];
        As[0][r][akq + 0] = to_tf32(a.x); As[0][r][akq + 1] = to_tf32(a.y);
        As[0][r][akq + 2] = to_tf32(a.z); As[0][r][akq + 3] = to_tf32(a.w);
        Bs[0][r][akq + 0] = to_tf32(b.x); Bs[0][r][akq + 1] = to_tf32(b.y);
        Bs[0][r][akq + 2] = to_tf32(b.z); Bs[0][r][akq + 3] = to_tf32(b.w);
    }
    __syncthreads();

    int buf = 0;
    const int KT = E / 16;   // 48
    for (int kt = 0; kt < KT; kt++) {
        float4 pa[2], pb[2];
        if (kt + 1 < KT) {
            const int k0 = (kt + 1) * 16;
#pragma unroll
            for (int s = 0; s < 2; s++) {
                const int r = arow0 + s * 64;
                pa[s] = *(const float4*)&X[(size_t)(row0 + r) * E + k0 + akq];
                pb[s] = *(const float4*)&W[(size_t)(col0 + r) * E + k0 + akq];
            }
        }
        mma_buffer<4>(As[buf], Bs[buf], acc, warp_m, warp_n, g, t);
        if (kt + 1 < KT) {
            const int nb = buf ^ 1;
#pragma unroll
            for (int s = 0; s < 2; s++) {
                const int r = arow0 + s * 64;
                As[nb][r][akq + 0] = to_tf32(pa[s].x); As[nb][r][akq + 1] = to_tf32(pa[s].y);
                As[nb][r][akq + 2] = to_tf32(pa[s].z); As[nb][r][akq + 3] = to_tf32(pa[s].w);
                Bs[nb][r][akq + 0] = to_tf32(pb[s].x); Bs[nb][r][akq + 1] = to_tf32(pb[s].y);
                Bs[nb][r][akq + 2] = to_tf32(pb[s].z); Bs[nb][r][akq + 3] = to_tf32(pb[s].w);
            }
            buf = nb;
        }
        __syncthreads();
    }

#pragma unroll
    for (int mt = 0; mt < 4; mt++) {
        const int r = row0 + warp_m * 64 + mt * 16 + g;
#pragma unroll
        for (int nt = 0; nt < 4; nt++) {
            const int c = col0 + warp_n * 32 + nt * 8 + 2 * t;
            const float bx = bias[c], by = bias[c + 1];
            const float v0x = acc[mt][nt].x + bx, v0y = acc[mt][nt].y + by;
            const float v1x = acc[mt][nt].z + bx, v1y = acc[mt][nt].w + by;
            if (QKV) {
                __half* out = (__half*)out_;
                const int bb_ = r >> 10, m = r & 1023;
                const int hh = c / D, d = c - hh * D;
                const size_t o0 = (((size_t)(bb_ * H + hh)) * NTOK + m) * D + d;
                const int bb2 = (r + 8) >> 10, m2 = (r + 8) & 1023;
                const size_t o1 = (((size_t)(bb2 * H + hh)) * NTOK + m2) * D + d;
                *(__half2*)&out[o0] = __floats2half2_rn(v0x, v0y);
                *(__half2*)&out[o1] = __floats2half2_rn(v1x, v1y);
            } else {
                float* out = (float*)out_;
                *(float2*)&out[(size_t)r * E + c] = make_float2(v0x, v0y);
                *(float2*)&out[(size_t)(r + 8) * E + c] = make_float2(v1x, v1y);
            }
        }
    }
}

// ---------------------------------------------------------------------------
// Scores: per z: S = scale * Q @ K^T (fp16 in, fp16 out, fp32 accum).
// 128x128 block, BK=32 halves, KT=3, NT=4 warp tile 64x32.
// ---------------------------------------------------------------------------
__launch_bounds__(256)
__global__ void scores_f16(const __half* __restrict__ Q,
                           const __half* __restrict__ K,
                           __half* __restrict__ S, float scale) {
    __shared__ uint32_t As[2][128][20];
    __shared__ uint32_t Bs[2][128][20];

    const int z = blockIdx.z;
    const __half* Qz = Q + (size_t)z * NTOK * D;
    const __half* Kz = K + (size_t)z * NTOK * D;
    __half* Sz = S + (size_t)z * NTOK * NTOK;

    const int tid = threadIdx.x;
    const int lane = tid & 31;
    const int w = tid >> 5;
    const int warp_m = w & 1, warp_n = w >> 1;
    const int g = lane >> 2, t = lane & 3;
    const int row0 = blockIdx.y * 128, col0 = blockIdx.x * 128;

    const int arow0 = tid >> 2;         // 0..63
    const int lq = (tid & 3) * 8;       // half offset within 32-half window

    float4 acc[4][4];
#pragma unroll
    for (int i = 0; i < 4; i++)
#pragma unroll
        for (int j = 0; j < 4; j++) acc[i][j] = make_float4(0.f, 0.f, 0.f, 0.f);

#pragma unroll
    for (int s = 0; s < 2; s++) {
        const int r = arow0 + s * 64;
        const uint4 a = *(const uint4*)&Qz[(size_t)(row0 + r) * D + lq];
        const uint4 b = *(const uint4*)&Kz[(size_t)(col0 + r) * D + lq];
        const int c0 = lq >> 1;
        As[0][r][c0 + 0] = a.x; As[0][r][c0 + 1] = a.y; As[0][r][c0 + 2] = a.z; As[0][r][c0 + 3] = a.w;
        Bs[0][r][c0 + 0] = b.x; Bs[0][r][c0 + 1] = b.y; Bs[0][r][c0 + 2] = b.z; Bs[0][r][c0 + 3] = b.w;
    }
    __syncthreads();

    int buf = 0;
    const int KT = D / 32;   // 3
    for (int kt = 0; kt < KT; kt++) {
        uint4 pa[2], pb[2];
        if (kt + 1 < KT) {
            const int k0 = (kt + 1) * 32;
#pragma unroll
            for (int s = 0; s < 2; s++) {
                const int r = arow0 + s * 64;
                pa[s] = *(const uint4*)&Qz[(size_t)(row0 + r) * D + k0 + lq];
                pb[s] = *(const uint4*)&Kz[(size_t)(col0 + r) * D + k0 + lq];
            }
        }
        mma_buffer16<4>(As[buf], Bs[buf], acc, warp_m, warp_n, g, t);
        if (kt + 1 < KT) {
            const int nb = buf ^ 1;
#pragma unroll
            for (int s = 0; s < 2; s++) {
                const int r = arow0 + s * 64;
                const int c0 = lq >> 1;
                As[nb][r][c0 + 0] = pa[s].x; As[nb][r][c0 + 1] = pa[s].y;
                As[nb][r][c0 + 2] = pa[s].z; As[nb][r][c0 + 3] = pa[s].w;
                Bs[nb][r][c0 + 0] = pb[s].x; Bs[nb][r][c0 + 1] = pb[s].y;
                Bs[nb][r][c0 + 2] = pb[s].z; Bs[nb][r][c0 + 3] = pb[s].w;
            }
            buf = nb;
        }
        __syncthreads();
    }

#pragma unroll
    for (int mt = 0; mt < 4; mt++) {
        const int m = row0 + warp_m * 64 + mt * 16 + g;
#pragma unroll
        for (int nt = 0; nt < 4; nt++) {
            const int p = col0 + warp_n * 32 + nt * 8 + 2 * t;
            *(__half2*)&Sz[(size_t)m * NTOK + p] =
                __floats2half2_rn(acc[mt][nt].x * scale, acc[mt][nt].y * scale);
            *(__half2*)&Sz[(size_t)(m + 8) * NTOK + p] =
                __floats2half2_rn(acc[mt][nt].z * scale, acc[mt][nt].w * scale);
        }
    }
}

// ---------------------------------------------------------------------------
// Fused softmax (in place, fp16) + head-average (fp32 out).
// One block per (b,m), warp per head; lane handles 32 contiguous halves x4 chunks.
// ---------------------------------------------------------------------------
__launch_bounds__(256)
__global__ void softmax_avg(__half* __restrict__ S, float* __restrict__ avg_out) {
    __shared__ float4 sm[8][256];
    const int bm = blockIdx.x;
    const int b = bm >> 10, m = bm & 1023;
    const int w = threadIdx.x >> 5, lane = threadIdx.x & 31;

    uint4* row = (uint4*)(S + (((size_t)(b * H + w)) * NTOK + m) * NTOK);  // 128 uint4
    float x[32];
    float mx = -INFINITY;
#pragma unroll
    for (int j = 0; j < 4; j++) {
        const uint4 u = row[lane + j * 32];
        const __half2* hp = (const __half2*)&u;
#pragma unroll
        for (int q = 0; q < 4; q++) {
            const float2 f = __half22float2(hp[q]);
            x[j * 8 + q * 2 + 0] = f.x;
            x[j * 8 + q * 2 + 1] = f.y;
            mx = fmaxf(mx, fmaxf(f.x, f.y));
        }
    }
#pragma unroll
    for (int o = 16; o > 0; o >>= 1) mx = fmaxf(mx, __shfl_xor_sync(0xffffffffu, mx, o));

    float sum = 0.f;
#pragma unroll
    for (int i = 0; i < 32; i++) {
        x[i] = __expf(x[i] - mx);
        sum += x[i];
    }
#pragma unroll
    for (int o = 16; o > 0; o >>= 1) sum += __shfl_xor_sync(0xffffffffu, sum, o);
    const float inv = 1.f / sum;

#pragma unroll
    for (int j = 0; j < 4; j++) {
        uint4 u;
        __half2* hp = (__half2*)&u;
        float4 lo, hi;
        lo.x = x[j * 8 + 0] * inv; lo.y = x[j * 8 + 1] * inv;
        lo.z = x[j * 8 + 2] * inv; lo.w = x[j * 8 + 3] * inv;
        hi.x = x[j * 8 + 4] * inv; hi.y = x[j * 8 + 5] * inv;
        hi.z = x[j * 8 + 6] * inv; hi.w = x[j * 8 + 7] * inv;
        hp[0] = __floats2half2_rn(lo.x, lo.y);
        hp[1] = __floats2half2_rn(lo.z, lo.w);
        hp[2] = __floats2half2_rn(hi.x, hi.y);
        hp[3] = __floats2half2_rn(hi.z, hi.w);
        row[lane + j * 32] = u;
        sm[w][(lane + j * 32) * 2 + 0] = lo;
        sm[w][(lane + j * 32) * 2 + 1] = hi;
    }
    __syncthreads();

    const int tt = threadIdx.x;
    float4 acc = make_float4(0.f, 0.f, 0.f, 0.f);
#pragma unroll
    for (int h = 0; h < 8; h++) {
        const float4 v = sm[h][tt];
        acc.x += v.x; acc.y += v.y; acc.z += v.z; acc.w += v.w;
    }
    acc.x *= 0.125f; acc.y *= 0.125f; acc.z *= 0.125f; acc.w *= 0.125f;
    ((float4*)(avg_out + (size_t)bm * NTOK))[tt] = acc;
}

// ---------------------------------------------------------------------------
// PV: per z: C[1024,96] = P[1024,1024] @ V[1024,96], fp16 in, fp32 out.
// 128x96 block, BK=32 halves, KT=32, NT=3 warp tile 64x24. V transposed in smem.
// ---------------------------------------------------------------------------
__launch_bounds__(256)
__global__ void pv_f16(const __half* __restrict__ S,
                       const __half* __restrict__ V,
                       float* __restrict__ A) {
    __shared__ uint32_t As[2][128][20];
    __shared__ uint32_t Bs[2][96][20];

    const int z = blockIdx.z;
    const int b = z >> 3, h = z & 7;
    const __half* Pz = S + (size_t)z * NTOK * NTOK;
    const __half* Vz = V + (size_t)z * NTOK * D;

    const int tid = threadIdx.x;
    const int lane = tid & 31;
    const int w = tid >> 5;
    const int warp_m = w & 1, warp_n = w >> 1;
    const int g = lane >> 2, t = lane & 3;
    const int row0 = blockIdx.y * 128;

    const int arow0 = tid >> 2;
    const int lq = (tid & 3) * 8;

    float4 acc[4][3];
#pragma unroll
    for (int i = 0; i < 4; i++)
#pragma unroll
        for (int j = 0; j < 3; j++) acc[i][j] = make_float4(0.f, 0.f, 0.f, 0.f);

    // initial fill
#pragma unroll
    for (int s = 0; s < 2; s++) {
        const int r = arow0 + s * 64;
        const uint4 a = *(const uint4*)&Pz[(size_t)(row0 + r) * NTOK + lq];
        const int c0 = lq >> 1;
        As[0][r][c0 + 0] = a.x; As[0][r][c0 + 1] = a.y; As[0][r][c0 + 2] = a.z; As[0][r][c0 + 3] = a.w;
    }
#pragma unroll
    for (int s = 0; s < 6; s++) {
        const int idx = tid + s * 256;        // 0..1535
        const int d = idx % D;                // 0..95
        const int j = idx / D;                // 0..15 (k-pair)
        Bs[0][d][j] = pack_half2(Vz[(size_t)(2 * j) * D + d], Vz[(size_t)(2 * j + 1) * D + d]);
    }
    __syncthreads();

    int buf = 0;
    const int KT = NTOK / 32;  // 32
    for (int kt = 0; kt < KT; kt++) {
        uint4 pa[2];
        uint32_t pvv[6];
        if (kt + 1 < KT) {
            const int k0 = (kt + 1) * 32;
#pragma unroll
            for (int s = 0; s < 2; s++) {
                const int r = arow0 + s * 64;
                pa[s] = *(const uint4*)&Pz[(size_t)(row0 + r) * NTOK + k0 + lq];
            }
#pragma unroll
            for (int s = 0; s < 6; s++) {
                const int idx = tid + s * 256;
                const int d = idx % D;
                const int j = idx / D;
                pvv[s] = pack_half2(Vz[(size_t)(k0 + 2 * j) * D + d],
                                    Vz[(size_t)(k0 + 2 * j + 1) * D + d]);
            }
        }
        mma_buffer16<3>(As[buf], Bs[buf], acc, warp_m, warp_n, g, t);
        if (kt + 1 < KT) {
            const int nb = buf ^ 1;
#pragma unroll
            for (int s = 0; s < 2; s++) {
                const int r = arow0 + s * 64;
                const int c0 = lq >> 1;
                As[nb][r][c0 + 0] = pa[s].x; As[nb][r][c0 + 1] = pa[s].y;
                As[nb][r][c0 + 2] = pa[s].z; As[nb][r][c0 + 3] = pa[s].w;
            }
#pragma unroll
            for (int s = 0; s < 6; s++) {
                const int idx = tid + s * 256;
                const int d = idx % D;
                const int j = idx / D;
                Bs[nb][d][j] = pvv[s];
            }
            buf = nb;
        }
        __syncthreads();
    }

#pragma unroll
    for (int mt = 0; mt < 4; mt++) {
        const int m = row0 + warp_m * 64 + mt * 16 + g;
#pragma unroll
        for (int nt = 0; nt < 3; nt++) {
            const int d = warp_n * 24 + nt * 8 + 2 * t;
            *(float2*)&A[((size_t)b * NTOK + m) * E + h * D + d] =
                make_float2(acc[mt][nt].x, acc[mt][nt].y);
            *(float2*)&A[((size_t)b * NTOK + m + 8) * E + h * D + d] =
                make_float2(acc[mt][nt].z, acc[mt][nt].w);
        }
    }
}

// ---------------------------------------------------------------------------
extern "C" void kernel_launch(void* const* d_in, const int* in_sizes, int n_in,
                              void* d_out, int out_size) {
    const float* mammo = (const float*)d_in[0];
    const float* patho = (const float*)d_in[1];
    const float* q_w = (const float*)d_in[2];
    const float* q_b = (const float*)d_in[3];
    const float* k_w = (const float*)d_in[4];
    const float* k_b = (const float*)d_in[5];
    const float* v_w = (const float*)d_in[6];
    const float* v_b = (const float*)d_in[7];
    const float* o_w = (const float*)d_in[8];
    const float* o_b = (const float*)d_in[9];

    float* out_attended = (float*)d_out;
    float* out_attn_avg = (float*)d_out + (size_t)B * NTOK * E;

    __half *Qp, *Kp, *Vp, *Sp;
    float *Ap;
    cudaGetSymbolAddress((void**)&Qp, g_Q);
    cudaGetSymbolAddress((void**)&Kp, g_K);
    cudaGetSymbolAddress((void**)&Vp, g_V);
    cudaGetSymbolAddress((void**)&Sp, g_S);
    cudaGetSymbolAddress((void**)&Ap, g_A);

    const dim3 lin_grid(E / 128, MROWS / 128);   // (6, 64)
    linear_tf32<1><<<lin_grid, 256>>>(mammo, q_w, q_b, Qp);
    linear_tf32<1><<<lin_grid, 256>>>(patho, k_w, k_b, Kp);
    linear_tf32<1><<<lin_grid, 256>>>(patho, v_w, v_b, Vp);

    const float scale = 1.0f / sqrtf((float)D);
    scores_f16<<<dim3(NTOK / 128, NTOK / 128, BHM), 256>>>(Qp, Kp, Sp, scale);

    softmax_avg<<<B * NTOK, 256>>>(Sp, out_attn_avg);

    pv_f16<<<dim3(1, NTOK / 128, BHM), 256>>>(Sp, Vp, Ap);

    linear_tf32<0><<<lin_grid, 256>>>(Ap, o_w, o_b, out_attended);
}

// round 6
// speedup vs baseline: 5.5641x; 1.4460x over previous
#include <cuda_runtime.h>
#include <cuda_fp16.h>
#include <math.h>
#include <stdint.h>

// Problem constants
#define B 8
#define NTOK 1024
#define E 768
#define H 8
#define D 96
#define BHM (B * H)
#define MROWS (B * NTOK)

// ---------------- device scratch (no allocations allowed) ----------------
__device__ __half g_Xm[MROWS * E];                       // fp16 mammo
__device__ __half g_Xp[MROWS * E];                       // fp16 patho
__device__ __half g_Wq[E * E];
__device__ __half g_Wk[E * E];
__device__ __half g_Wv[E * E];
__device__ __half g_Wo[E * E];
__device__ __half g_Q[B * H * NTOK * D];                 // fp16 [b,h,m,d]
__device__ __half g_K[B * H * NTOK * D];
__device__ __half g_V[B * H * NTOK * D];
__device__ __half g_S[(size_t)BHM * NTOK * NTOK];        // 128 MB scores -> probs
__device__ __half g_A[B * NTOK * E];                     // attended pre-O (fp16)

// ---------------------------------------------------------------------------
__device__ __forceinline__ uint32_t pack_half2(__half lo, __half hi) {
    __half2 h = __halves2half2(lo, hi);
    return *reinterpret_cast<uint32_t*>(&h);
}

__device__ __forceinline__ void mma_f16(float4& c, const uint32_t a[4], const uint32_t b[2]) {
    asm volatile(
        "mma.sync.aligned.m16n8k16.row.col.f32.f16.f16.f32 "
        "{%0,%1,%2,%3}, {%4,%5,%6,%7}, {%8,%9}, {%0,%1,%2,%3};"
        : "+f"(c.x), "+f"(c.y), "+f"(c.z), "+f"(c.w)
        : "r"(a[0]), "r"(a[1]), "r"(a[2]), "r"(a[3]), "r"(b[0]), "r"(b[1]));
}

// fp16: one BK=32(halves) buffer. As: uint32 [128][20] (m, kpair); Bs: [BN][20].
template <int NT>
__device__ __forceinline__ void mma_buffer16(const uint32_t (*As)[20], const uint32_t (*Bs)[20],
                                             float4 acc[4][NT],
                                             int warp_m, int warp_n, int g, int t) {
#pragma unroll
    for (int ks = 0; ks < 2; ks++) {
        const int kc = ks * 8;
        uint32_t af[4][4];
#pragma unroll
        for (int mt = 0; mt < 4; mt++) {
            const int r = warp_m * 64 + mt * 16;
            af[mt][0] = As[r + g][kc + t];
            af[mt][1] = As[r + g + 8][kc + t];
            af[mt][2] = As[r + g][kc + t + 4];
            af[mt][3] = As[r + g + 8][kc + t + 4];
        }
        uint32_t bf[NT][2];
#pragma unroll
        for (int nt = 0; nt < NT; nt++) {
            const int cbase = warp_n * (NT * 8) + nt * 8;
            bf[nt][0] = Bs[cbase + g][kc + t];
            bf[nt][1] = Bs[cbase + g][kc + t + 4];
        }
#pragma unroll
        for (int mt = 0; mt < 4; mt++)
#pragma unroll
            for (int nt = 0; nt < NT; nt++) mma_f16(acc[mt][nt], af[mt], bf[nt]);
    }
}

// ---------------------------------------------------------------------------
// fp32 -> fp16 elementwise convert (n % 8 == 0)
// ---------------------------------------------------------------------------
__global__ void cvt_f16(const float* __restrict__ src, __half* __restrict__ dst, int n) {
    const int i = (blockIdx.x * blockDim.x + threadIdx.x) * 8;
    if (i >= n) return;
    const float4 a = *(const float4*)&src[i];
    const float4 b = *(const float4*)&src[i + 4];
    uint4 u;
    u.x = pack_half2(__float2half_rn(a.x), __float2half_rn(a.y));
    u.y = pack_half2(__float2half_rn(a.z), __float2half_rn(a.w));
    u.z = pack_half2(__float2half_rn(b.x), __float2half_rn(b.y));
    u.w = pack_half2(__float2half_rn(b.z), __float2half_rn(b.w));
    *(uint4*)&dst[i] = u;
}

// ---------------------------------------------------------------------------
// Linear (fp16 in, fp32 accum): C[M,768] = X[M,768] @ W[768,768]^T + bias
// 128x128 block, BK=32 halves, KT=24, NT=4 warp tile 64x32.
// QKV=1: write fp16 to [b,h,m,d]; QKV=0: write fp32 row-major.
// ---------------------------------------------------------------------------
template <int QKV>
__launch_bounds__(256)
__global__ void linear_f16(const __half* __restrict__ X,
                           const __half* __restrict__ W,
                           const float* __restrict__ bias,
                           void* __restrict__ out_) {
    __shared__ uint32_t As[2][128][20];
    __shared__ uint32_t Bs[2][128][20];

    const int tid = threadIdx.x;
    const int lane = tid & 31;
    const int w = tid >> 5;
    const int warp_m = w & 1, warp_n = w >> 1;
    const int g = lane >> 2, t = lane & 3;
    const int row0 = blockIdx.y * 128, col0 = blockIdx.x * 128;

    const int arow0 = tid >> 2;         // 0..63
    const int lq = (tid & 3) * 8;       // half offset in 32-half window

    float4 acc[4][4];
#pragma unroll
    for (int i = 0; i < 4; i++)
#pragma unroll
        for (int j = 0; j < 4; j++) acc[i][j] = make_float4(0.f, 0.f, 0.f, 0.f);

#pragma unroll
    for (int s = 0; s < 2; s++) {
        const int r = arow0 + s * 64;
        const uint4 a = *(const uint4*)&X[(size_t)(row0 + r) * E + lq];
        const uint4 b = *(const uint4*)&W[(size_t)(col0 + r) * E + lq];
        const int c0 = lq >> 1;
        As[0][r][c0 + 0] = a.x; As[0][r][c0 + 1] = a.y; As[0][r][c0 + 2] = a.z; As[0][r][c0 + 3] = a.w;
        Bs[0][r][c0 + 0] = b.x; Bs[0][r][c0 + 1] = b.y; Bs[0][r][c0 + 2] = b.z; Bs[0][r][c0 + 3] = b.w;
    }
    __syncthreads();

    int buf = 0;
    const int KT = E / 32;   // 24
    for (int kt = 0; kt < KT; kt++) {
        uint4 pa[2], pb[2];
        if (kt + 1 < KT) {
            const int k0 = (kt + 1) * 32;
#pragma unroll
            for (int s = 0; s < 2; s++) {
                const int r = arow0 + s * 64;
                pa[s] = *(const uint4*)&X[(size_t)(row0 + r) * E + k0 + lq];
                pb[s] = *(const uint4*)&W[(size_t)(col0 + r) * E + k0 + lq];
            }
        }
        mma_buffer16<4>(As[buf], Bs[buf], acc, warp_m, warp_n, g, t);
        if (kt + 1 < KT) {
            const int nb = buf ^ 1;
#pragma unroll
            for (int s = 0; s < 2; s++) {
                const int r = arow0 + s * 64;
                const int c0 = lq >> 1;
                As[nb][r][c0 + 0] = pa[s].x; As[nb][r][c0 + 1] = pa[s].y;
                As[nb][r][c0 + 2] = pa[s].z; As[nb][r][c0 + 3] = pa[s].w;
                Bs[nb][r][c0 + 0] = pb[s].x; Bs[nb][r][c0 + 1] = pb[s].y;
                Bs[nb][r][c0 + 2] = pb[s].z; Bs[nb][r][c0 + 3] = pb[s].w;
            }
            buf = nb;
        }
        __syncthreads();
    }

#pragma unroll
    for (int mt = 0; mt < 4; mt++) {
        const int r = row0 + warp_m * 64 + mt * 16 + g;
#pragma unroll
        for (int nt = 0; nt < 4; nt++) {
            const int c = col0 + warp_n * 32 + nt * 8 + 2 * t;
            const float bx = bias[c], by = bias[c + 1];
            const float v0x = acc[mt][nt].x + bx, v0y = acc[mt][nt].y + by;
            const float v1x = acc[mt][nt].z + bx, v1y = acc[mt][nt].w + by;
            if (QKV) {
                __half* out = (__half*)out_;
                const int bb_ = r >> 10, m = r & 1023;
                const int hh = c / D, d = c - hh * D;
                const size_t o0 = (((size_t)(bb_ * H + hh)) * NTOK + m) * D + d;
                const int bb2 = (r + 8) >> 10, m2 = (r + 8) & 1023;
                const size_t o1 = (((size_t)(bb2 * H + hh)) * NTOK + m2) * D + d;
                *(__half2*)&out[o0] = __floats2half2_rn(v0x, v0y);
                *(__half2*)&out[o1] = __floats2half2_rn(v1x, v1y);
            } else {
                float* out = (float*)out_;
                *(float2*)&out[(size_t)r * E + c] = make_float2(v0x, v0y);
                *(float2*)&out[(size_t)(r + 8) * E + c] = make_float2(v1x, v1y);
            }
        }
    }
}

// ---------------------------------------------------------------------------
// Scores: per z: S = scale * Q @ K^T (fp16 in/out, fp32 accum).
// ---------------------------------------------------------------------------
__launch_bounds__(256)
__global__ void scores_f16(const __half* __restrict__ Q,
                           const __half* __restrict__ K,
                           __half* __restrict__ S, float scale) {
    __shared__ uint32_t As[2][128][20];
    __shared__ uint32_t Bs[2][128][20];

    const int z = blockIdx.z;
    const __half* Qz = Q + (size_t)z * NTOK * D;
    const __half* Kz = K + (size_t)z * NTOK * D;
    __half* Sz = S + (size_t)z * NTOK * NTOK;

    const int tid = threadIdx.x;
    const int lane = tid & 31;
    const int w = tid >> 5;
    const int warp_m = w & 1, warp_n = w >> 1;
    const int g = lane >> 2, t = lane & 3;
    const int row0 = blockIdx.y * 128, col0 = blockIdx.x * 128;

    const int arow0 = tid >> 2;
    const int lq = (tid & 3) * 8;

    float4 acc[4][4];
#pragma unroll
    for (int i = 0; i < 4; i++)
#pragma unroll
        for (int j = 0; j < 4; j++) acc[i][j] = make_float4(0.f, 0.f, 0.f, 0.f);

#pragma unroll
    for (int s = 0; s < 2; s++) {
        const int r = arow0 + s * 64;
        const uint4 a = *(const uint4*)&Qz[(size_t)(row0 + r) * D + lq];
        const uint4 b = *(const uint4*)&Kz[(size_t)(col0 + r) * D + lq];
        const int c0 = lq >> 1;
        As[0][r][c0 + 0] = a.x; As[0][r][c0 + 1] = a.y; As[0][r][c0 + 2] = a.z; As[0][r][c0 + 3] = a.w;
        Bs[0][r][c0 + 0] = b.x; Bs[0][r][c0 + 1] = b.y; Bs[0][r][c0 + 2] = b.z; Bs[0][r][c0 + 3] = b.w;
    }
    __syncthreads();

    int buf = 0;
    const int KT = D / 32;   // 3
    for (int kt = 0; kt < KT; kt++) {
        uint4 pa[2], pb[2];
        if (kt + 1 < KT) {
            const int k0 = (kt + 1) * 32;
#pragma unroll
            for (int s = 0; s < 2; s++) {
                const int r = arow0 + s * 64;
                pa[s] = *(const uint4*)&Qz[(size_t)(row0 + r) * D + k0 + lq];
                pb[s] = *(const uint4*)&Kz[(size_t)(col0 + r) * D + k0 + lq];
            }
        }
        mma_buffer16<4>(As[buf], Bs[buf], acc, warp_m, warp_n, g, t);
        if (kt + 1 < KT) {
            const int nb = buf ^ 1;
#pragma unroll
            for (int s = 0; s < 2; s++) {
                const int r = arow0 + s * 64;
                const int c0 = lq >> 1;
                As[nb][r][c0 + 0] = pa[s].x; As[nb][r][c0 + 1] = pa[s].y;
                As[nb][r][c0 + 2] = pa[s].z; As[nb][r][c0 + 3] = pa[s].w;
                Bs[nb][r][c0 + 0] = pb[s].x; Bs[nb][r][c0 + 1] = pb[s].y;
                Bs[nb][r][c0 + 2] = pb[s].z; Bs[nb][r][c0 + 3] = pb[s].w;
            }
            buf = nb;
        }
        __syncthreads();
    }

#pragma unroll
    for (int mt = 0; mt < 4; mt++) {
        const int m = row0 + warp_m * 64 + mt * 16 + g;
#pragma unroll
        for (int nt = 0; nt < 4; nt++) {
            const int p = col0 + warp_n * 32 + nt * 8 + 2 * t;
            *(__half2*)&Sz[(size_t)m * NTOK + p] =
                __floats2half2_rn(acc[mt][nt].x * scale, acc[mt][nt].y * scale);
            *(__half2*)&Sz[(size_t)(m + 8) * NTOK + p] =
                __floats2half2_rn(acc[mt][nt].z * scale, acc[mt][nt].w * scale);
        }
    }
}

// ---------------------------------------------------------------------------
// Fused softmax (in place, fp16) + head-average (fp32 out).
// ---------------------------------------------------------------------------
__launch_bounds__(256)
__global__ void softmax_avg(__half* __restrict__ S, float* __restrict__ avg_out) {
    __shared__ float4 sm[8][256];
    const int bm = blockIdx.x;
    const int b = bm >> 10, m = bm & 1023;
    const int w = threadIdx.x >> 5, lane = threadIdx.x & 31;

    uint4* row = (uint4*)(S + (((size_t)(b * H + w)) * NTOK + m) * NTOK);
    float x[32];
    float mx = -INFINITY;
#pragma unroll
    for (int j = 0; j < 4; j++) {
        const uint4 u = row[lane + j * 32];
        const __half2* hp = (const __half2*)&u;
#pragma unroll
        for (int q = 0; q < 4; q++) {
            const float2 f = __half22float2(hp[q]);
            x[j * 8 + q * 2 + 0] = f.x;
            x[j * 8 + q * 2 + 1] = f.y;
            mx = fmaxf(mx, fmaxf(f.x, f.y));
        }
    }
#pragma unroll
    for (int o = 16; o > 0; o >>= 1) mx = fmaxf(mx, __shfl_xor_sync(0xffffffffu, mx, o));

    float sum = 0.f;
#pragma unroll
    for (int i = 0; i < 32; i++) {
        x[i] = __expf(x[i] - mx);
        sum += x[i];
    }
#pragma unroll
    for (int o = 16; o > 0; o >>= 1) sum += __shfl_xor_sync(0xffffffffu, sum, o);
    const float inv = 1.f / sum;

#pragma unroll
    for (int j = 0; j < 4; j++) {
        uint4 u;
        __half2* hp = (__half2*)&u;
        float4 lo, hi;
        lo.x = x[j * 8 + 0] * inv; lo.y = x[j * 8 + 1] * inv;
        lo.z = x[j * 8 + 2] * inv; lo.w = x[j * 8 + 3] * inv;
        hi.x = x[j * 8 + 4] * inv; hi.y = x[j * 8 + 5] * inv;
        hi.z = x[j * 8 + 6] * inv; hi.w = x[j * 8 + 7] * inv;
        hp[0] = __floats2half2_rn(lo.x, lo.y);
        hp[1] = __floats2half2_rn(lo.z, lo.w);
        hp[2] = __floats2half2_rn(hi.x, hi.y);
        hp[3] = __floats2half2_rn(hi.z, hi.w);
        row[lane + j * 32] = u;
        sm[w][(lane + j * 32) * 2 + 0] = lo;
        sm[w][(lane + j * 32) * 2 + 1] = hi;
    }
    __syncthreads();

    const int tt = threadIdx.x;
    float4 acc = make_float4(0.f, 0.f, 0.f, 0.f);
#pragma unroll
    for (int h = 0; h < 8; h++) {
        const float4 v = sm[h][tt];
        acc.x += v.x; acc.y += v.y; acc.z += v.z; acc.w += v.w;
    }
    acc.x *= 0.125f; acc.y *= 0.125f; acc.z *= 0.125f; acc.w *= 0.125f;
    ((float4*)(avg_out + (size_t)bm * NTOK))[tt] = acc;
}

// ---------------------------------------------------------------------------
// PV: per z: C[1024,96] = P[1024,1024] @ V[1024,96], fp16 in, fp16 out.
// ---------------------------------------------------------------------------
__launch_bounds__(256)
__global__ void pv_f16(const __half* __restrict__ S,
                       const __half* __restrict__ V,
                       __half* __restrict__ A) {
    __shared__ uint32_t As[2][128][20];
    __shared__ uint32_t Bs[2][96][20];

    const int z = blockIdx.z;
    const int b = z >> 3, h = z & 7;
    const __half* Pz = S + (size_t)z * NTOK * NTOK;
    const __half* Vz = V + (size_t)z * NTOK * D;

    const int tid = threadIdx.x;
    const int lane = tid & 31;
    const int w = tid >> 5;
    const int warp_m = w & 1, warp_n = w >> 1;
    const int g = lane >> 2, t = lane & 3;
    const int row0 = blockIdx.y * 128;

    const int arow0 = tid >> 2;
    const int lq = (tid & 3) * 8;

    float4 acc[4][3];
#pragma unroll
    for (int i = 0; i < 4; i++)
#pragma unroll
        for (int j = 0; j < 3; j++) acc[i][j] = make_float4(0.f, 0.f, 0.f, 0.f);

#pragma unroll
    for (int s = 0; s < 2; s++) {
        const int r = arow0 + s * 64;
        const uint4 a = *(const uint4*)&Pz[(size_t)(row0 + r) * NTOK + lq];
        const int c0 = lq >> 1;
        As[0][r][c0 + 0] = a.x; As[0][r][c0 + 1] = a.y; As[0][r][c0 + 2] = a.z; As[0][r][c0 + 3] = a.w;
    }
#pragma unroll
    for (int s = 0; s < 6; s++) {
        const int idx = tid + s * 256;
        const int d = idx % D;
        const int j = idx / D;
        Bs[0][d][j] = pack_half2(Vz[(size_t)(2 * j) * D + d], Vz[(size_t)(2 * j + 1) * D + d]);
    }
    __syncthreads();

    int buf = 0;
    const int KT = NTOK / 32;  // 32
    for (int kt = 0; kt < KT; kt++) {
        uint4 pa[2];
        uint32_t pvv[6];
        if (kt + 1 < KT) {
            const int k0 = (kt + 1) * 32;
#pragma unroll
            for (int s = 0; s < 2; s++) {
                const int r = arow0 + s * 64;
                pa[s] = *(const uint4*)&Pz[(size_t)(row0 + r) * NTOK + k0 + lq];
            }
#pragma unroll
            for (int s = 0; s < 6; s++) {
                const int idx = tid + s * 256;
                const int d = idx % D;
                const int j = idx / D;
                pvv[s] = pack_half2(Vz[(size_t)(k0 + 2 * j) * D + d],
                                    Vz[(size_t)(k0 + 2 * j + 1) * D + d]);
            }
        }
        mma_buffer16<3>(As[buf], Bs[buf], acc, warp_m, warp_n, g, t);
        if (kt + 1 < KT) {
            const int nb = buf ^ 1;
#pragma unroll
            for (int s = 0; s < 2; s++) {
                const int r = arow0 + s * 64;
                const int c0 = lq >> 1;
                As[nb][r][c0 + 0] = pa[s].x; As[nb][r][c0 + 1] = pa[s].y;
                As[nb][r][c0 + 2] = pa[s].z; As[nb][r][c0 + 3] = pa[s].w;
            }
#pragma unroll
            for (int s = 0; s < 6; s++) {
                const int idx = tid + s * 256;
                const int d = idx % D;
                const int j = idx / D;
                Bs[nb][d][j] = pvv[s];
            }
            buf = nb;
        }
        __syncthreads();
    }

#pragma unroll
    for (int mt = 0; mt < 4; mt++) {
        const int m = row0 + warp_m * 64 + mt * 16 + g;
#pragma unroll
        for (int nt = 0; nt < 3; nt++) {
            const int d = warp_n * 24 + nt * 8 + 2 * t;
            *(__half2*)&A[((size_t)b * NTOK + m) * E + h * D + d] =
                __floats2half2_rn(acc[mt][nt].x, acc[mt][nt].y);
            *(__half2*)&A[((size_t)b * NTOK + m + 8) * E + h * D + d] =
                __floats2half2_rn(acc[mt][nt].z, acc[mt][nt].w);
        }
    }
}

// ---------------------------------------------------------------------------
extern "C" void kernel_launch(void* const* d_in, const int* in_sizes, int n_in,
                              void* d_out, int out_size) {
    const float* mammo = (const float*)d_in[0];
    const float* patho = (const float*)d_in[1];
    const float* q_w = (const float*)d_in[2];
    const float* q_b = (const float*)d_in[3];
    const float* k_w = (const float*)d_in[4];
    const float* k_b = (const float*)d_in[5];
    const float* v_w = (const float*)d_in[6];
    const float* v_b = (const float*)d_in[7];
    const float* o_w = (const float*)d_in[8];
    const float* o_b = (const float*)d_in[9];

    float* out_attended = (float*)d_out;
    float* out_attn_avg = (float*)d_out + (size_t)B * NTOK * E;

    __half *Xm, *Xp, *Wq, *Wk, *Wv, *Wo, *Qp, *Kp, *Vp, *Sp, *Ap;
    cudaGetSymbolAddress((void**)&Xm, g_Xm);
    cudaGetSymbolAddress((void**)&Xp, g_Xp);
    cudaGetSymbolAddress((void**)&Wq, g_Wq);
    cudaGetSymbolAddress((void**)&Wk, g_Wk);
    cudaGetSymbolAddress((void**)&Wv, g_Wv);
    cudaGetSymbolAddress((void**)&Wo, g_Wo);
    cudaGetSymbolAddress((void**)&Qp, g_Q);
    cudaGetSymbolAddress((void**)&Kp, g_K);
    cudaGetSymbolAddress((void**)&Vp, g_V);
    cudaGetSymbolAddress((void**)&Sp, g_S);
    cudaGetSymbolAddress((void**)&Ap, g_A);

    const int NX = MROWS * E;    // 6291456
    const int NW = E * E;        // 589824
    cvt_f16<<<NX / (256 * 8), 256>>>(mammo, Xm, NX);
    cvt_f16<<<NX / (256 * 8), 256>>>(patho, Xp, NX);
    cvt_f16<<<NW / (256 * 8), 256>>>(q_w, Wq, NW);
    cvt_f16<<<NW / (256 * 8), 256>>>(k_w, Wk, NW);
    cvt_f16<<<NW / (256 * 8), 256>>>(v_w, Wv, NW);
    cvt_f16<<<NW / (256 * 8), 256>>>(o_w, Wo, NW);

    const dim3 lin_grid(E / 128, MROWS / 128);   // (6, 64)
    linear_f16<1><<<lin_grid, 256>>>(Xm, Wq, q_b, Qp);
    linear_f16<1><<<lin_grid, 256>>>(Xp, Wk, k_b, Kp);
    linear_f16<1><<<lin_grid, 256>>>(Xp, Wv, v_b, Vp);

    const float scale = 1.0f / sqrtf((float)D);
    scores_f16<<<dim3(NTOK / 128, NTOK / 128, BHM), 256>>>(Qp, Kp, Sp, scale);

    softmax_avg<<<B * NTOK, 256>>>(Sp, out_attn_avg);

    pv_f16<<<dim3(1, NTOK / 128, BHM), 256>>>(Sp, Vp, Ap);

    linear_f16<0><<<lin_grid, 256>>>(Ap, Wo, o_b, out_attended);
}

// round 7
// speedup vs baseline: 5.6179x; 1.0097x over previous
#include <cuda_runtime.h>
#include <cuda_fp16.h>
#include <math.h>
#include <stdint.h>

// Problem constants
#define B 8
#define NTOK 1024
#define E 768
#define H 8
#define D 96
#define BHM (B * H)
#define MROWS (B * NTOK)

// ---------------- device scratch (no allocations allowed) ----------------
__device__ __half g_Xm[MROWS * E];
__device__ __half g_Xp[MROWS * E];
__device__ __half g_Wq[E * E];
__device__ __half g_Wk[E * E];
__device__ __half g_Wv[E * E];
__device__ __half g_Wo[E * E];
__device__ __half g_Q[B * H * NTOK * D];
__device__ __half g_K[B * H * NTOK * D];
__device__ __half g_V[B * H * NTOK * D];
__device__ __half g_S[(size_t)BHM * NTOK * NTOK];
__device__ __half g_A[B * NTOK * E];

// ---------------------------------------------------------------------------
__device__ __forceinline__ uint32_t pack_half2(__half lo, __half hi) {
    __half2 h = __halves2half2(lo, hi);
    return *reinterpret_cast<uint32_t*>(&h);
}

__device__ __forceinline__ uint32_t smem_u32(const void* p) {
    uint32_t a;
    asm("{ .reg .u64 t; cvta.to.shared.u64 t, %1; cvt.u32.u64 %0, t; }"
        : "=r"(a) : "l"(p));
    return a;
}

__device__ __forceinline__ void ldsm_x4(uint32_t& r0, uint32_t& r1, uint32_t& r2, uint32_t& r3,
                                        uint32_t addr) {
    asm volatile("ldmatrix.sync.aligned.m8n8.x4.shared.b16 {%0,%1,%2,%3}, [%4];"
                 : "=r"(r0), "=r"(r1), "=r"(r2), "=r"(r3) : "r"(addr));
}

__device__ __forceinline__ void ldsm_x2(uint32_t& r0, uint32_t& r1, uint32_t addr) {
    asm volatile("ldmatrix.sync.aligned.m8n8.x2.shared.b16 {%0,%1}, [%2];"
                 : "=r"(r0), "=r"(r1) : "r"(addr));
}

__device__ __forceinline__ void mma_f16(float4& c, const uint32_t a[4], const uint32_t b[2]) {
    asm volatile(
        "mma.sync.aligned.m16n8k16.row.col.f32.f16.f16.f32 "
        "{%0,%1,%2,%3}, {%4,%5,%6,%7}, {%8,%9}, {%0,%1,%2,%3};"
        : "+f"(c.x), "+f"(c.y), "+f"(c.z), "+f"(c.w)
        : "r"(a[0]), "r"(a[1]), "r"(a[2]), "r"(a[3]), "r"(b[0]), "r"(b[1]));
}

// One BK=32-half buffer using ldmatrix.
// As/Bs layout: uint32 [rows][20], row = m (or n), cols 0..15 = k-pairs.
// as_base/bs_base: shared-space byte addresses of the current buffer.
template <int NT>
__device__ __forceinline__ void mma_ldsm(uint32_t as_base, uint32_t bs_base,
                                         float4 acc[4][NT],
                                         int warp_m, int warp_n, int lane) {
    // A: lane l -> matrix i = l/8; i0:(R,kb) i1:(R+8,kb) i2:(R,kb+4) i3:(R+8,kb+4)
    const uint32_t arow = (uint32_t)(warp_m * 64 + (lane & 7) + ((lane >> 3) & 1) * 8);
    const uint32_t acol = (uint32_t)((lane >> 4) * 4);
    const uint32_t a_off = as_base + (arow * 20 + acol) * 4;
    // B x4: i0:(tile0,kb) i1:(tile0,kb+4) i2:(tile1,kb) i3:(tile1,kb+4)
    const uint32_t brow = (uint32_t)((lane & 7) + (lane >> 4) * 8);
    const uint32_t bcol = (uint32_t)(((lane >> 3) & 1) * 4);
    const uint32_t cb = (uint32_t)(warp_n * NT * 8);
    const uint32_t b_off = bs_base + ((cb + brow) * 20 + bcol) * 4;

#pragma unroll
    for (int ks = 0; ks < 2; ks++) {
        uint32_t af[4][4];
#pragma unroll
        for (int mt = 0; mt < 4; mt++)
            ldsm_x4(af[mt][0], af[mt][1], af[mt][2], af[mt][3],
                    a_off + (uint32_t)((mt * 16 * 20 + ks * 8) * 4));

        uint32_t bf[NT][2];
#pragma unroll
        for (int p = 0; p < NT / 2; p++)
            ldsm_x4(bf[2 * p][0], bf[2 * p][1], bf[2 * p + 1][0], bf[2 * p + 1][1],
                    b_off + (uint32_t)((p * 16 * 20 + ks * 8) * 4));
        if (NT & 1) {
            // last tile via x2: lanes 0-15 pattern (repeats for 16-31, ignored)
            const uint32_t row2 = cb + (uint32_t)((NT - 1) * 8) + (uint32_t)(lane & 7);
            const uint32_t col2 = (uint32_t)(((lane >> 3) & 1) * 4);
            ldsm_x2(bf[NT - 1][0], bf[NT - 1][1],
                    bs_base + (row2 * 20 + col2 + (uint32_t)(ks * 8)) * 4);
        }

#pragma unroll
        for (int mt = 0; mt < 4; mt++)
#pragma unroll
            for (int nt = 0; nt < NT; nt++) mma_f16(acc[mt][nt], af[mt], bf[nt]);
    }
}

// ---------------------------------------------------------------------------
// Fused fp32 -> fp16 convert of all 6 tensors. Block = 2048 elements.
// ---------------------------------------------------------------------------
#define NXBLK (MROWS * E / 2048)      // 3072
#define NWBLK (E * E / 2048)          // 288
__global__ void cvt_all(const float* __restrict__ m, const float* __restrict__ p,
                        const float* __restrict__ qw, const float* __restrict__ kw,
                        const float* __restrict__ vw, const float* __restrict__ ow) {
    int blk = blockIdx.x;
    const float* src;
    __half* dst;
    if (blk < NXBLK)                { src = m;  dst = g_Xm; }
    else if (blk < 2 * NXBLK)       { src = p;  dst = g_Xp; blk -= NXBLK; }
    else if (blk < 2 * NXBLK + NWBLK)       { src = qw; dst = g_Wq; blk -= 2 * NXBLK; }
    else if (blk < 2 * NXBLK + 2 * NWBLK)   { src = kw; dst = g_Wk; blk -= 2 * NXBLK + NWBLK; }
    else if (blk < 2 * NXBLK + 3 * NWBLK)   { src = vw; dst = g_Wv; blk -= 2 * NXBLK + 2 * NWBLK; }
    else                                    { src = ow; dst = g_Wo; blk -= 2 * NXBLK + 3 * NWBLK; }
    const int i = blk * 2048 + threadIdx.x * 8;
    const float4 a = *(const float4*)&src[i];
    const float4 b = *(const float4*)&src[i + 4];
    uint4 u;
    u.x = pack_half2(__float2half_rn(a.x), __float2half_rn(a.y));
    u.y = pack_half2(__float2half_rn(a.z), __float2half_rn(a.w));
    u.z = pack_half2(__float2half_rn(b.x), __float2half_rn(b.y));
    u.w = pack_half2(__float2half_rn(b.z), __float2half_rn(b.w));
    *(uint4*)&dst[i] = u;
}

// ---------------------------------------------------------------------------
// Linear (fp16 in, fp32 accum): C[M,768] = X @ W^T + bias
// QKV=1: write fp16 to [b,h,m,d]; QKV=0: write fp32 row-major.
// ---------------------------------------------------------------------------
template <int QKV>
__launch_bounds__(256)
__global__ void linear_f16(const __half* __restrict__ X,
                           const __half* __restrict__ W,
                           const float* __restrict__ bias,
                           void* __restrict__ out_) {
    __shared__ uint32_t As[2][128][20];
    __shared__ uint32_t Bs[2][128][20];

    const int tid = threadIdx.x;
    const int lane = tid & 31;
    const int w = tid >> 5;
    const int warp_m = w & 1, warp_n = w >> 1;
    const int g = lane >> 2, t = lane & 3;
    const int row0 = blockIdx.y * 128, col0 = blockIdx.x * 128;

    const int arow0 = tid >> 2;
    const int lq = (tid & 3) * 8;

    const uint32_t as0 = smem_u32(&As[0][0][0]);
    const uint32_t bs0 = smem_u32(&Bs[0][0][0]);
    const uint32_t bufsz = 128 * 20 * 4;

    float4 acc[4][4];
#pragma unroll
    for (int i = 0; i < 4; i++)
#pragma unroll
        for (int j = 0; j < 4; j++) acc[i][j] = make_float4(0.f, 0.f, 0.f, 0.f);

#pragma unroll
    for (int s = 0; s < 2; s++) {
        const int r = arow0 + s * 64;
        const uint4 a = *(const uint4*)&X[(size_t)(row0 + r) * E + lq];
        const uint4 b = *(const uint4*)&W[(size_t)(col0 + r) * E + lq];
        const int c0 = lq >> 1;
        As[0][r][c0 + 0] = a.x; As[0][r][c0 + 1] = a.y; As[0][r][c0 + 2] = a.z; As[0][r][c0 + 3] = a.w;
        Bs[0][r][c0 + 0] = b.x; Bs[0][r][c0 + 1] = b.y; Bs[0][r][c0 + 2] = b.z; Bs[0][r][c0 + 3] = b.w;
    }
    __syncthreads();

    int buf = 0;
    const int KT = E / 32;   // 24
    for (int kt = 0; kt < KT; kt++) {
        uint4 pa[2], pb[2];
        if (kt + 1 < KT) {
            const int k0 = (kt + 1) * 32;
#pragma unroll
            for (int s = 0; s < 2; s++) {
                const int r = arow0 + s * 64;
                pa[s] = *(const uint4*)&X[(size_t)(row0 + r) * E + k0 + lq];
                pb[s] = *(const uint4*)&W[(size_t)(col0 + r) * E + k0 + lq];
            }
        }
        mma_ldsm<4>(as0 + buf * bufsz, bs0 + buf * bufsz, acc, warp_m, warp_n, lane);
        if (kt + 1 < KT) {
            const int nb = buf ^ 1;
#pragma unroll
            for (int s = 0; s < 2; s++) {
                const int r = arow0 + s * 64;
                const int c0 = lq >> 1;
                As[nb][r][c0 + 0] = pa[s].x; As[nb][r][c0 + 1] = pa[s].y;
                As[nb][r][c0 + 2] = pa[s].z; As[nb][r][c0 + 3] = pa[s].w;
                Bs[nb][r][c0 + 0] = pb[s].x; Bs[nb][r][c0 + 1] = pb[s].y;
                Bs[nb][r][c0 + 2] = pb[s].z; Bs[nb][r][c0 + 3] = pb[s].w;
            }
            buf = nb;
        }
        __syncthreads();
    }

#pragma unroll
    for (int mt = 0; mt < 4; mt++) {
        const int r = row0 + warp_m * 64 + mt * 16 + g;
#pragma unroll
        for (int nt = 0; nt < 4; nt++) {
            const int c = col0 + warp_n * 32 + nt * 8 + 2 * t;
            const float bx = bias[c], by = bias[c + 1];
            const float v0x = acc[mt][nt].x + bx, v0y = acc[mt][nt].y + by;
            const float v1x = acc[mt][nt].z + bx, v1y = acc[mt][nt].w + by;
            if (QKV) {
                __half* out = (__half*)out_;
                const int bb_ = r >> 10, m = r & 1023;
                const int hh = c / D, d = c - hh * D;
                const size_t o0 = (((size_t)(bb_ * H + hh)) * NTOK + m) * D + d;
                const int bb2 = (r + 8) >> 10, m2 = (r + 8) & 1023;
                const size_t o1 = (((size_t)(bb2 * H + hh)) * NTOK + m2) * D + d;
                *(__half2*)&out[o0] = __floats2half2_rn(v0x, v0y);
                *(__half2*)&out[o1] = __floats2half2_rn(v1x, v1y);
            } else {
                float* out = (float*)out_;
                *(float2*)&out[(size_t)r * E + c] = make_float2(v0x, v0y);
                *(float2*)&out[(size_t)(r + 8) * E + c] = make_float2(v1x, v1y);
            }
        }
    }
}

// ---------------------------------------------------------------------------
// Scores: per z: S = scale * Q @ K^T (fp16 in/out, fp32 accum).
// ---------------------------------------------------------------------------
__launch_bounds__(256)
__global__ void scores_f16(const __half* __restrict__ Q,
                           const __half* __restrict__ K,
                           __half* __restrict__ S, float scale) {
    __shared__ uint32_t As[2][128][20];
    __shared__ uint32_t Bs[2][128][20];

    const int z = blockIdx.z;
    const __half* Qz = Q + (size_t)z * NTOK * D;
    const __half* Kz = K + (size_t)z * NTOK * D;
    __half* Sz = S + (size_t)z * NTOK * NTOK;

    const int tid = threadIdx.x;
    const int lane = tid & 31;
    const int w = tid >> 5;
    const int warp_m = w & 1, warp_n = w >> 1;
    const int g = lane >> 2, t = lane & 3;
    const int row0 = blockIdx.y * 128, col0 = blockIdx.x * 128;

    const int arow0 = tid >> 2;
    const int lq = (tid & 3) * 8;

    const uint32_t as0 = smem_u32(&As[0][0][0]);
    const uint32_t bs0 = smem_u32(&Bs[0][0][0]);
    const uint32_t bufsz = 128 * 20 * 4;

    float4 acc[4][4];
#pragma unroll
    for (int i = 0; i < 4; i++)
#pragma unroll
        for (int j = 0; j < 4; j++) acc[i][j] = make_float4(0.f, 0.f, 0.f, 0.f);

#pragma unroll
    for (int s = 0; s < 2; s++) {
        const int r = arow0 + s * 64;
        const uint4 a = *(const uint4*)&Qz[(size_t)(row0 + r) * D + lq];
        const uint4 b = *(const uint4*)&Kz[(size_t)(col0 + r) * D + lq];
        const int c0 = lq >> 1;
        As[0][r][c0 + 0] = a.x; As[0][r][c0 + 1] = a.y; As[0][r][c0 + 2] = a.z; As[0][r][c0 + 3] = a.w;
        Bs[0][r][c0 + 0] = b.x; Bs[0][r][c0 + 1] = b.y; Bs[0][r][c0 + 2] = b.z; Bs[0][r][c0 + 3] = b.w;
    }
    __syncthreads();

    int buf = 0;
    const int KT = D / 32;   // 3
    for (int kt = 0; kt < KT; kt++) {
        uint4 pa[2], pb[2];
        if (kt + 1 < KT) {
            const int k0 = (kt + 1) * 32;
#pragma unroll
            for (int s = 0; s < 2; s++) {
                const int r = arow0 + s * 64;
                pa[s] = *(const uint4*)&Qz[(size_t)(row0 + r) * D + k0 + lq];
                pb[s] = *(const uint4*)&Kz[(size_t)(col0 + r) * D + k0 + lq];
            }
        }
        mma_ldsm<4>(as0 + buf * bufsz, bs0 + buf * bufsz, acc, warp_m, warp_n, lane);
        if (kt + 1 < KT) {
            const int nb = buf ^ 1;
#pragma unroll
            for (int s = 0; s < 2; s++) {
                const int r = arow0 + s * 64;
                const int c0 = lq >> 1;
                As[nb][r][c0 + 0] = pa[s].x; As[nb][r][c0 + 1] = pa[s].y;
                As[nb][r][c0 + 2] = pa[s].z; As[nb][r][c0 + 3] = pa[s].w;
                Bs[nb][r][c0 + 0] = pb[s].x; Bs[nb][r][c0 + 1] = pb[s].y;
                Bs[nb][r][c0 + 2] = pb[s].z; Bs[nb][r][c0 + 3] = pb[s].w;
            }
            buf = nb;
        }
        __syncthreads();
    }

#pragma unroll
    for (int mt = 0; mt < 4; mt++) {
        const int m = row0 + warp_m * 64 + mt * 16 + g;
#pragma unroll
        for (int nt = 0; nt < 4; nt++) {
            const int p = col0 + warp_n * 32 + nt * 8 + 2 * t;
            *(__half2*)&Sz[(size_t)m * NTOK + p] =
                __floats2half2_rn(acc[mt][nt].x * scale, acc[mt][nt].y * scale);
            *(__half2*)&Sz[(size_t)(m + 8) * NTOK + p] =
                __floats2half2_rn(acc[mt][nt].z * scale, acc[mt][nt].w * scale);
        }
    }
}

// ---------------------------------------------------------------------------
// Fused softmax (in place, fp16) + head-average (fp32 out).
// ---------------------------------------------------------------------------
__launch_bounds__(256)
__global__ void softmax_avg(__half* __restrict__ S, float* __restrict__ avg_out) {
    __shared__ float4 sm[8][256];
    const int bm = blockIdx.x;
    const int b = bm >> 10, m = bm & 1023;
    const int w = threadIdx.x >> 5, lane = threadIdx.x & 31;

    uint4* row = (uint4*)(S + (((size_t)(b * H + w)) * NTOK + m) * NTOK);
    float x[32];
    float mx = -INFINITY;
#pragma unroll
    for (int j = 0; j < 4; j++) {
        const uint4 u = row[lane + j * 32];
        const __half2* hp = (const __half2*)&u;
#pragma unroll
        for (int q = 0; q < 4; q++) {
            const float2 f = __half22float2(hp[q]);
            x[j * 8 + q * 2 + 0] = f.x;
            x[j * 8 + q * 2 + 1] = f.y;
            mx = fmaxf(mx, fmaxf(f.x, f.y));
        }
    }
#pragma unroll
    for (int o = 16; o > 0; o >>= 1) mx = fmaxf(mx, __shfl_xor_sync(0xffffffffu, mx, o));

    float sum = 0.f;
#pragma unroll
    for (int i = 0; i < 32; i++) {
        x[i] = __expf(x[i] - mx);
        sum += x[i];
    }
#pragma unroll
    for (int o = 16; o > 0; o >>= 1) sum += __shfl_xor_sync(0xffffffffu, sum, o);
    const float inv = 1.f / sum;

#pragma unroll
    for (int j = 0; j < 4; j++) {
        uint4 u;
        __half2* hp = (__half2*)&u;
        float4 lo, hi;
        lo.x = x[j * 8 + 0] * inv; lo.y = x[j * 8 + 1] * inv;
        lo.z = x[j * 8 + 2] * inv; lo.w = x[j * 8 + 3] * inv;
        hi.x = x[j * 8 + 4] * inv; hi.y = x[j * 8 + 5] * inv;
        hi.z = x[j * 8 + 6] * inv; hi.w = x[j * 8 + 7] * inv;
        hp[0] = __floats2half2_rn(lo.x, lo.y);
        hp[1] = __floats2half2_rn(lo.z, lo.w);
        hp[2] = __floats2half2_rn(hi.x, hi.y);
        hp[3] = __floats2half2_rn(hi.z, hi.w);
        row[lane + j * 32] = u;
        sm[w][(lane + j * 32) * 2 + 0] = lo;
        sm[w][(lane + j * 32) * 2 + 1] = hi;
    }
    __syncthreads();

    const int tt = threadIdx.x;
    float4 acc = make_float4(0.f, 0.f, 0.f, 0.f);
#pragma unroll
    for (int h = 0; h < 8; h++) {
        const float4 v = sm[h][tt];
        acc.x += v.x; acc.y += v.y; acc.z += v.z; acc.w += v.w;
    }
    acc.x *= 0.125f; acc.y *= 0.125f; acc.z *= 0.125f; acc.w *= 0.125f;
    ((float4*)(avg_out + (size_t)bm * NTOK))[tt] = acc;
}

// ---------------------------------------------------------------------------
// PV: per z: C[1024,96] = P[1024,1024] @ V[1024,96], fp16 in/out.
// ---------------------------------------------------------------------------
__launch_bounds__(256)
__global__ void pv_f16(const __half* __restrict__ S,
                       const __half* __restrict__ V,
                       __half* __restrict__ A) {
    __shared__ uint32_t As[2][128][20];
    __shared__ uint32_t Bs[2][96][20];

    const int z = blockIdx.z;
    const int b = z >> 3, h = z & 7;
    const __half* Pz = S + (size_t)z * NTOK * NTOK;
    const __half* Vz = V + (size_t)z * NTOK * D;

    const int tid = threadIdx.x;
    const int lane = tid & 31;
    const int w = tid >> 5;
    const int warp_m = w & 1, warp_n = w >> 1;
    const int g = lane >> 2, t = lane & 3;
    const int row0 = blockIdx.y * 128;

    const int arow0 = tid >> 2;
    const int lq = (tid & 3) * 8;

    const uint32_t as0 = smem_u32(&As[0][0][0]);
    const uint32_t bs0 = smem_u32(&Bs[0][0][0]);
    const uint32_t absz = 128 * 20 * 4;
    const uint32_t bbsz = 96 * 20 * 4;

    float4 acc[4][3];
#pragma unroll
    for (int i = 0; i < 4; i++)
#pragma unroll
        for (int j = 0; j < 3; j++) acc[i][j] = make_float4(0.f, 0.f, 0.f, 0.f);

#pragma unroll
    for (int s = 0; s < 2; s++) {
        const int r = arow0 + s * 64;
        const uint4 a = *(const uint4*)&Pz[(size_t)(row0 + r) * NTOK + lq];
        const int c0 = lq >> 1;
        As[0][r][c0 + 0] = a.x; As[0][r][c0 + 1] = a.y; As[0][r][c0 + 2] = a.z; As[0][r][c0 + 3] = a.w;
    }
#pragma unroll
    for (int s = 0; s < 6; s++) {
        const int idx = tid + s * 256;
        const int d = idx % D;
        const int j = idx / D;
        Bs[0][d][j] = pack_half2(Vz[(size_t)(2 * j) * D + d], Vz[(size_t)(2 * j + 1) * D + d]);
    }
    __syncthreads();

    int buf = 0;
    const int KT = NTOK / 32;  // 32
    for (int kt = 0; kt < KT; kt++) {
        uint4 pa[2];
        uint32_t pvv[6];
        if (kt + 1 < KT) {
            const int k0 = (kt + 1) * 32;
#pragma unroll
            for (int s = 0; s < 2; s++) {
                const int r = arow0 + s * 64;
                pa[s] = *(const uint4*)&Pz[(size_t)(row0 + r) * NTOK + k0 + lq];
            }
#pragma unroll
            for (int s = 0; s < 6; s++) {
                const int idx = tid + s * 256;
                const int d = idx % D;
                const int j = idx / D;
                pvv[s] = pack_half2(Vz[(size_t)(k0 + 2 * j) * D + d],
                                    Vz[(size_t)(k0 + 2 * j + 1) * D + d]);
            }
        }
        mma_ldsm<3>(as0 + buf * absz, bs0 + buf * bbsz, acc, warp_m, warp_n, lane);
        if (kt + 1 < KT) {
            const int nb = buf ^ 1;
#pragma unroll
            for (int s = 0; s < 2; s++) {
                const int r = arow0 + s * 64;
                const int c0 = lq >> 1;
                As[nb][r][c0 + 0] = pa[s].x; As[nb][r][c0 + 1] = pa[s].y;
                As[nb][r][c0 + 2] = pa[s].z; As[nb][r][c0 + 3] = pa[s].w;
            }
#pragma unroll
            for (int s = 0; s < 6; s++) {
                const int idx = tid + s * 256;
                const int d = idx % D;
                const int j = idx / D;
                Bs[nb][d][j] = pvv[s];
            }
            buf = nb;
        }
        __syncthreads();
    }

#pragma unroll
    for (int mt = 0; mt < 4; mt++) {
        const int m = row0 + warp_m * 64 + mt * 16 + g;
#pragma unroll
        for (int nt = 0; nt < 3; nt++) {
            const int d = warp_n * 24 + nt * 8 + 2 * t;
            *(__half2*)&A[((size_t)b * NTOK + m) * E + h * D + d] =
                __floats2half2_rn(acc[mt][nt].x, acc[mt][nt].y);
            *(__half2*)&A[((size_t)b * NTOK + m + 8) * E + h * D + d] =
                __floats2half2_rn(acc[mt][nt].z, acc[mt][nt].w);
        }
    }
}

// ---------------------------------------------------------------------------
extern "C" void kernel_launch(void* const* d_in, const int* in_sizes, int n_in,
                              void* d_out, int out_size) {
    const float* mammo = (const float*)d_in[0];
    const float* patho = (const float*)d_in[1];
    const float* q_w = (const float*)d_in[2];
    const float* q_b = (const float*)d_in[3];
    const float* k_w = (const float*)d_in[4];
    const float* k_b = (const float*)d_in[5];
    const float* v_w = (const float*)d_in[6];
    const float* v_b = (const float*)d_in[7];
    const float* o_w = (const float*)d_in[8];
    const float* o_b = (const float*)d_in[9];

    float* out_attended = (float*)d_out;
    float* out_attn_avg = (float*)d_out + (size_t)B * NTOK * E;

    __half *Xm, *Xp, *Wq, *Wk, *Wv, *Wo, *Qp, *Kp, *Vp, *Sp, *Ap;
    cudaGetSymbolAddress((void**)&Xm, g_Xm);
    cudaGetSymbolAddress((void**)&Xp, g_Xp);
    cudaGetSymbolAddress((void**)&Wq, g_Wq);
    cudaGetSymbolAddress((void**)&Wk, g_Wk);
    cudaGetSymbolAddress((void**)&Wv, g_Wv);
    cudaGetSymbolAddress((void**)&Wo, g_Wo);
    cudaGetSymbolAddress((void**)&Qp, g_Q);
    cudaGetSymbolAddress((void**)&Kp, g_K);
    cudaGetSymbolAddress((void**)&Vp, g_V);
    cudaGetSymbolAddress((void**)&Sp, g_S);
    cudaGetSymbolAddress((void**)&Ap, g_A);

    cvt_all<<<2 * NXBLK + 4 * NWBLK, 256>>>(mammo, patho, q_w, k_w, v_w, o_w);

    const dim3 lin_grid(E / 128, MROWS / 128);   // (6, 64)
    linear_f16<1><<<lin_grid, 256>>>(Xm, Wq, q_b, Qp);
    linear_f16<1><<<lin_grid, 256>>>(Xp, Wk, k_b, Kp);
    linear_f16<1><<<lin_grid, 256>>>(Xp, Wv, v_b, Vp);

    const float scale = 1.0f / sqrtf((float)D);
    scores_f16<<<dim3(NTOK / 128, NTOK / 128, BHM), 256>>>(Qp, Kp, Sp, scale);

    softmax_avg<<<B * NTOK, 256>>>(Sp, out_attn_avg);

    pv_f16<<<dim3(1, NTOK / 128, BHM), 256>>>(Sp, Vp, Ap);

    linear_f16<0><<<lin_grid, 256>>>(Ap, Wo, o_b, out_attended);
}